// round 12
// baseline (speedup 1.0000x reference)
#include <cuda_runtime.h>
#include <cuda_bf16.h>
#include <cstdint>

// Problem dims
#define BB   64
#define SS   512
#define DD   1024
#define HH   1024
#define RT   (BB*SS)
#define EPS  1e-6f

// ---------------- device scratch (static; no runtime allocs) ----------------
__device__ __align__(16) __nv_bfloat16 g_xh[2][(size_t)RT * DD];
__device__ __align__(16) __nv_bfloat16 g_xl[2][(size_t)RT * DD];
__device__ __align__(16) __nv_bfloat16 g_wh[2][(size_t)HH * DD];
__device__ __align__(16) __nv_bfloat16 g_wl[2][(size_t)HH * DD];
__device__ float g_gamma[BB * HH];
__device__ float g_alpha[BB * HH];
__device__ float g_part[2][8][RT];
__device__ float g_wbuf[BB * SS];
__device__ float g_ctx_part[4][BB * DD];
__device__ float g_fin_part[4][BB * HH];

// =====================================================================
// FMA-only tanh (no MUFU); abs err ~3e-7.
// =====================================================================
__device__ __forceinline__ float tanh_fma(float x) {
    float ax = fabsf(x);
    float t  = fminf(ax * 2.885390081777927f, 30.0f);
    float k  = __fadd_rn(t, 12582912.0f);
    int   n  = __float_as_int(k) - 0x4B400000;
    float fn = __fadd_rn(k, -12582912.0f);
    float f  = __fadd_rn(t, -fn);
    float p = 1.5402387e-4f;
    p = fmaf(p, f, 1.3333558e-3f);
    p = fmaf(p, f, 9.6181291e-3f);
    p = fmaf(p, f, 5.5504109e-2f);
    p = fmaf(p, f, 2.4022651e-1f);
    p = fmaf(p, f, 6.9314718e-1f);
    p = fmaf(p, f, 1.0f);
    float E = p * __int_as_float(0x3f800000 + (n << 23));
    float d = E + 1.0f;
    float y = __int_as_float(0x7EF311C3 - __float_as_int(d));
    y = y * fmaf(-d, y, 2.0f);
    y = y * fmaf(-d, y, 2.0f);
    y = y * fmaf(-d, y, 2.0f);
    float r = fmaf(-2.0f, y, 1.0f);
    return copysignf(r, x);
}

// =====================================================================
// sm_80-portable PTX helpers
// =====================================================================
__device__ __forceinline__ uint32_t smem_u32(const void* p) {
    uint32_t a;
    asm("{ .reg .u64 t; cvta.to.shared.u64 t, %1; cvt.u32.u64 %0, t; }" : "=r"(a) : "l"(p));
    return a;
}
__device__ __forceinline__ void cp_async16(uint32_t dst, const void* src) {
    asm volatile("cp.async.cg.shared.global [%0], [%1], 16;" :: "r"(dst), "l"(src));
}
__device__ __forceinline__ void cp_commit() { asm volatile("cp.async.commit_group;" ::: "memory"); }
__device__ __forceinline__ void cp_wait1()  { asm volatile("cp.async.wait_group 1;" ::: "memory"); }

__device__ __forceinline__ void ldm_x4(uint32_t a, uint32_t& r0, uint32_t& r1,
                                       uint32_t& r2, uint32_t& r3) {
    asm volatile("ldmatrix.sync.aligned.m8n8.x4.shared.b16 {%0,%1,%2,%3}, [%4];"
                 : "=r"(r0), "=r"(r1), "=r"(r2), "=r"(r3) : "r"(a));
}
__device__ __forceinline__ void mma16816(float& c0, float& c1, float& c2, float& c3,
                                         uint32_t a0, uint32_t a1, uint32_t a2, uint32_t a3,
                                         uint32_t b0, uint32_t b1) {
    asm volatile("mma.sync.aligned.m16n8k16.row.col.f32.bf16.bf16.f32 "
                 "{%0,%1,%2,%3}, {%4,%5,%6,%7}, {%8,%9}, {%0,%1,%2,%3};"
                 : "+f"(c0), "+f"(c1), "+f"(c2), "+f"(c3)
                 : "r"(a0), "r"(a1), "r"(a2), "r"(a3), "r"(b0), "r"(b1));
}

// =====================================================================
// hi/lo split packer
// =====================================================================
__device__ __forceinline__ void split_pack(float4 v0, float4 v1, uint4& hp, uint4& lp) {
    __nv_bfloat16 h0 = __float2bfloat16(v0.x), h1 = __float2bfloat16(v0.y);
    __nv_bfloat16 h2 = __float2bfloat16(v0.z), h3 = __float2bfloat16(v0.w);
    __nv_bfloat16 h4 = __float2bfloat16(v1.x), h5 = __float2bfloat16(v1.y);
    __nv_bfloat16 h6 = __float2bfloat16(v1.z), h7 = __float2bfloat16(v1.w);
    __nv_bfloat16 l0 = __float2bfloat16(v0.x - __bfloat162float(h0));
    __nv_bfloat16 l1 = __float2bfloat16(v0.y - __bfloat162float(h1));
    __nv_bfloat16 l2 = __float2bfloat16(v0.z - __bfloat162float(h2));
    __nv_bfloat16 l3 = __float2bfloat16(v0.w - __bfloat162float(h3));
    __nv_bfloat16 l4 = __float2bfloat16(v1.x - __bfloat162float(h4));
    __nv_bfloat16 l5 = __float2bfloat16(v1.y - __bfloat162float(h5));
    __nv_bfloat16 l6 = __float2bfloat16(v1.z - __bfloat162float(h6));
    __nv_bfloat16 l7 = __float2bfloat16(v1.w - __bfloat162float(h7));
    hp.x = ((uint32_t)__bfloat16_as_ushort(h1) << 16) | __bfloat16_as_ushort(h0);
    hp.y = ((uint32_t)__bfloat16_as_ushort(h3) << 16) | __bfloat16_as_ushort(h2);
    hp.z = ((uint32_t)__bfloat16_as_ushort(h5) << 16) | __bfloat16_as_ushort(h4);
    hp.w = ((uint32_t)__bfloat16_as_ushort(h7) << 16) | __bfloat16_as_ushort(h6);
    lp.x = ((uint32_t)__bfloat16_as_ushort(l1) << 16) | __bfloat16_as_ushort(l0);
    lp.y = ((uint32_t)__bfloat16_as_ushort(l3) << 16) | __bfloat16_as_ushort(l2);
    lp.z = ((uint32_t)__bfloat16_as_ushort(l5) << 16) | __bfloat16_as_ushort(l4);
    lp.w = ((uint32_t)__bfloat16_as_ushort(l7) << 16) | __bfloat16_as_ushort(l6);
}

// =====================================================================
// prep_all: ALL pre-score work in ONE launch. grid (4096, 3), block 256.
//   y=0: cvt_x(hidden -> z0 planes)         [4096 blocks]
//   y=1: cvt_x(field  -> z1 planes)         [4096 blocks]
//   y=2: x<128: cvt_w(W1,0); x<256: cvt_w(W4,1);
//        x in [256,272): gamma; x in [272,288): alpha; else exit.
// =====================================================================
__global__ __launch_bounds__(256)
void prep_all(const float* __restrict__ hidden, const float* __restrict__ field,
              const float* __restrict__ W1g, const float* __restrict__ W4g,
              const float* __restrict__ inp,
              const float* __restrict__ W2, const float* __restrict__ b2,
              const float* __restrict__ W5, const float* __restrict__ b5)
{
    const int y = blockIdx.y;
    const int bx = blockIdx.x;
    const int tid = threadIdx.x;

    if (y < 2) {
        // ---- cvt_x (R11 measured-good MLP-8 body) ----
        const float* src = y ? field : hidden;
        uint4* dh = reinterpret_cast<uint4*>(g_xh[y]);
        uint4* dl = reinterpret_cast<uint4*>(g_xl[y]);
        const float4* s4 = reinterpret_cast<const float4*>(src);
        float4 v[8];
        size_t base[4];
        #pragma unroll
        for (int it = 0; it < 4; ++it) {
            size_t g8 = (size_t)bx * 1024 + it * 256 + tid;
            base[it] = g8;
            v[it * 2]     = s4[g8 * 2];
            v[it * 2 + 1] = s4[g8 * 2 + 1];
        }
        #pragma unroll
        for (int it = 0; it < 4; ++it) {
            uint4 hp, lp;
            split_pack(v[it * 2], v[it * 2 + 1], hp, lp);
            dh[base[it]] = hp;
            dl[base[it]] = lp;
        }
        return;
    }

    if (bx < 256) {
        // ---- cvt_w: z = bx>=128, local block index bx&127 ----
        const int z = bx >> 7;
        const int lb = bx & 127;
        const float* src = z ? W4g : W1g;
        uint4* dh = reinterpret_cast<uint4*>(g_wh[z]);
        uint4* dl = reinterpret_cast<uint4*>(g_wl[z]);
        const float4* s4 = reinterpret_cast<const float4*>(src);
        #pragma unroll
        for (int it = 0; it < 4; ++it) {
            size_t g8 = (size_t)lb * 1024 + it * 256 + tid;
            float4 v0 = s4[g8 * 2];
            float4 v1 = s4[g8 * 2 + 1];
            uint4 hp, lp;
            split_pack(v0, v1, hp, lp);
            dh[g8] = hp;
            dl[g8] = lp;
        }
        return;
    }
    if (bx >= 288) return;

    // ---- gamma/alpha small GEMM: z = (bx-256)>=16, col block = (bx-256)&15 ----
    const int q = bx - 256;
    const int z = q >> 4;
    const float* W    = z ? W5 : W2;
    const float* bias = z ? b5 : b2;
    float* out        = z ? g_alpha : g_gamma;

    const int colBase = (q & 15) * 64;
    __shared__ float As[16][64];
    __shared__ float Bs[16][64];

    const int tx = tid & 15;
    const int ty = tid >> 4;
    float acc[4][4] = {};

    for (int k0 = 0; k0 < DD; k0 += 16) {
        #pragma unroll
        for (int i = tid; i < 64 * 16; i += 256) {
            int m = i >> 4, kk = i & 15;
            As[kk][m] = inp[m * DD + k0 + kk];
            Bs[kk][m] = W[(colBase + m) * DD + k0 + kk];
        }
        __syncthreads();
        #pragma unroll
        for (int kk = 0; kk < 16; kk++) {
            float a[4], w[4];
            #pragma unroll
            for (int i = 0; i < 4; i++) a[i] = As[kk][ty * 4 + i];
            #pragma unroll
            for (int j = 0; j < 4; j++) w[j] = Bs[kk][tx * 4 + j];
            #pragma unroll
            for (int i = 0; i < 4; i++)
                #pragma unroll
                for (int j = 0; j < 4; j++) acc[i][j] += a[i] * w[j];
        }
        __syncthreads();
    }
    #pragma unroll
    for (int i = 0; i < 4; i++) {
        int b = ty * 4 + i;
        #pragma unroll
        for (int j = 0; j < 4; j++) {
            int h = colBase + tx * 4 + j;
            out[b * HH + h] = tanh_fma(acc[i][j] + bias[h]);
        }
    }
}

// =====================================================================
// Score GEMM — EXACT R4/R7/R11 structure (measured best).
// mma.sync bf16 3-term split, CTA 128x128, kc=32, 2-stage cp.async,
// 8 warps m32xn64, ROWB=80. grid (8, 256, 2), block 256.
// =====================================================================
#define KCH        32
#define NCHUNK     (DD / KCH)             // 32
#define ROWB       80                      // 64B data + 16B pad
#define TILEB      (128 * ROWB)            // 10240
#define STAGEB     (4 * TILEB)             // 40960
#define SM_BIAS    (2 * STAGEB)            // 81920
#define SM_GAM     (SM_BIAS + 512)
#define SM_SPART   (SM_GAM + 512)
#define SM_TOTAL   (SM_SPART + 1024)       // 83968

__global__ __launch_bounds__(256)
void score_mma_kernel(const float* __restrict__ b1g, const float* __restrict__ b4g)
{
    extern __shared__ char sm[];
    const uint32_t sb = smem_u32(sm);

    const int z       = blockIdx.z;
    const int colBase = blockIdx.x * 128;
    const int rowBase = blockIdx.y * 128;
    const int tid     = threadIdx.x;
    const int lane    = tid & 31;
    const int wid     = tid >> 5;
    const int wm      = wid >> 1;         // 0..3
    const int wn      = wid & 1;          // 0..1

    const __nv_bfloat16* Ah = g_xh[z] + (size_t)rowBase * DD;
    const __nv_bfloat16* Al = g_xl[z] + (size_t)rowBase * DD;
    const __nv_bfloat16* Bh = g_wh[z] + (size_t)colBase * DD;
    const __nv_bfloat16* Bl = g_wl[z] + (size_t)colBase * DD;
    const float* bias = z ? b4g : b1g;
    const float* gm   = z ? g_alpha : g_gamma;
    const int b_idx   = rowBase / SS;

    float* sbias = reinterpret_cast<float*>(sm + SM_BIAS);
    float* sgam  = reinterpret_cast<float*>(sm + SM_GAM);
    float* spart = reinterpret_cast<float*>(sm + SM_SPART);   // [128][2]

    if (tid < 128) {
        sbias[tid] = bias[colBase + tid];
        sgam[tid]  = gm[b_idx * HH + colBase + tid];
    }

    // ---- cp.async stage loader: 4 tiles x 128 rows x 4 segs = 2048 x16B ----
    auto load_stage = [&](int ch, int buf) {
        const uint32_t sbase = sb + buf * STAGEB;
        const int kb = ch * KCH * 2;      // byte offset in bf16 row
        #pragma unroll
        for (int q = 0; q < 8; ++q) {
            int idx  = q * 256 + tid;     // 0..2047
            int tile = idx >> 9;          // /512
            int rem  = idx & 511;
            int row  = rem >> 2;
            int seg  = (rem & 3) << 4;    // 0,16,32,48
            const char* src;
            switch (tile) {
                case 0:  src = (const char*)(Ah + (size_t)row * DD) + kb + seg; break;
                case 1:  src = (const char*)(Al + (size_t)row * DD) + kb + seg; break;
                case 2:  src = (const char*)(Bh + (size_t)row * DD) + kb + seg; break;
                default: src = (const char*)(Bl + (size_t)row * DD) + kb + seg; break;
            }
            cp_async16(sbase + tile * TILEB + row * ROWB + seg, src);
        }
    };

    float c[2][8][4];
    #pragma unroll
    for (int mt = 0; mt < 2; ++mt)
        #pragma unroll
        for (int j = 0; j < 8; ++j)
            #pragma unroll
            for (int e = 0; e < 4; ++e) c[mt][j][e] = 0.0f;

    load_stage(0, 0); cp_commit();
    load_stage(1, 1); cp_commit();

    const int t4  = lane >> 3;            // ldmatrix tile select
    const int r8  = lane & 7;

    for (int ch = 0; ch < NCHUNK; ++ch) {
        cp_wait1();
        __syncthreads();
        const uint32_t sbase = sb + (ch & 1) * STAGEB;
        const uint32_t aHi = sbase;
        const uint32_t aLo = sbase + TILEB;
        const uint32_t bHi = sbase + 2 * TILEB;
        const uint32_t bLo = sbase + 3 * TILEB;

        #pragma unroll
        for (int ks = 0; ks < 2; ++ks) {
            const int koff = ks * 32 + ((t4 >> 1) << 4);    // A k-byte
            const int koffB = ks * 32 + ((t4 & 1) << 4);    // B k-byte
            uint32_t ah[2][4], al[2][4];
            #pragma unroll
            for (int mt = 0; mt < 2; ++mt) {
                const int row = wm * 32 + mt * 16 + r8 + ((t4 & 1) << 3);
                ldm_x4(aHi + row * ROWB + koff, ah[mt][0], ah[mt][1], ah[mt][2], ah[mt][3]);
                ldm_x4(aLo + row * ROWB + koff, al[mt][0], al[mt][1], al[mt][2], al[mt][3]);
            }
            uint32_t bh[8][2], bl[8][2];
            #pragma unroll
            for (int nt = 0; nt < 4; ++nt) {
                const int row = wn * 64 + nt * 16 + r8 + ((t4 >> 1) << 3);
                uint32_t r0, r1, r2, r3;
                ldm_x4(bHi + row * ROWB + koffB, r0, r1, r2, r3);
                bh[nt * 2][0] = r0; bh[nt * 2][1] = r1;
                bh[nt * 2 + 1][0] = r2; bh[nt * 2 + 1][1] = r3;
                ldm_x4(bLo + row * ROWB + koffB, r0, r1, r2, r3);
                bl[nt * 2][0] = r0; bl[nt * 2][1] = r1;
                bl[nt * 2 + 1][0] = r2; bl[nt * 2 + 1][1] = r3;
            }
            // term sweeps: 16 independent accums between same-acc reuses
            #pragma unroll
            for (int mt = 0; mt < 2; ++mt)
                #pragma unroll
                for (int j = 0; j < 8; ++j)
                    mma16816(c[mt][j][0], c[mt][j][1], c[mt][j][2], c[mt][j][3],
                             ah[mt][0], ah[mt][1], ah[mt][2], ah[mt][3],
                             bh[j][0], bh[j][1]);
            #pragma unroll
            for (int mt = 0; mt < 2; ++mt)
                #pragma unroll
                for (int j = 0; j < 8; ++j)
                    mma16816(c[mt][j][0], c[mt][j][1], c[mt][j][2], c[mt][j][3],
                             ah[mt][0], ah[mt][1], ah[mt][2], ah[mt][3],
                             bl[j][0], bl[j][1]);
            #pragma unroll
            for (int mt = 0; mt < 2; ++mt)
                #pragma unroll
                for (int j = 0; j < 8; ++j)
                    mma16816(c[mt][j][0], c[mt][j][1], c[mt][j][2], c[mt][j][3],
                             al[mt][0], al[mt][1], al[mt][2], al[mt][3],
                             bh[j][0], bh[j][1]);
        }
        __syncthreads();
        if (ch + 2 < NCHUNK) load_stage(ch + 2, ch & 1);
        cp_commit();
    }

    // ---- epilogue: tanh + dot(gamma), reduce to per-row score partials ----
    float rsum[2][2] = {};
    #pragma unroll
    for (int mt = 0; mt < 2; ++mt) {
        #pragma unroll
        for (int j = 0; j < 8; ++j) {
            const int col0 = wn * 64 + j * 8 + (lane & 3) * 2;
            float b0 = sbias[col0], b1v = sbias[col0 + 1];
            float g0 = sgam[col0],  g1v = sgam[col0 + 1];
            rsum[mt][0] = fmaf(tanh_fma(c[mt][j][0] + b0), g0, rsum[mt][0]);
            rsum[mt][0] = fmaf(tanh_fma(c[mt][j][1] + b1v), g1v, rsum[mt][0]);
            rsum[mt][1] = fmaf(tanh_fma(c[mt][j][2] + b0), g0, rsum[mt][1]);
            rsum[mt][1] = fmaf(tanh_fma(c[mt][j][3] + b1v), g1v, rsum[mt][1]);
        }
    }
    #pragma unroll
    for (int mt = 0; mt < 2; ++mt)
        #pragma unroll
        for (int h = 0; h < 2; ++h) {
            float v = rsum[mt][h];
            v += __shfl_xor_sync(0xffffffffu, v, 1);
            v += __shfl_xor_sync(0xffffffffu, v, 2);
            rsum[mt][h] = v;
        }
    if ((lane & 3) == 0) {
        #pragma unroll
        for (int mt = 0; mt < 2; ++mt)
            #pragma unroll
            for (int h = 0; h < 2; ++h) {
                int r = wm * 32 + mt * 16 + (lane >> 2) + h * 8;
                spart[r * 2 + wn] = rsum[mt][h];
            }
    }
    __syncthreads();
    if (tid < 128)
        g_part[z][blockIdx.x][rowBase + tid] = spart[tid * 2] + spart[tid * 2 + 1];
}

// =====================================================================
// softmax combine (exact reference semantics)
// =====================================================================
__global__ __launch_bounds__(512)
void softmax_kernel(float* __restrict__ out, int w_off)
{
    const int b = blockIdx.x;
    const int s = threadIdx.x;
    const int r = b * SS + s;

    float sh = 0.0f, sf = 0.0f;
    #pragma unroll
    for (int nb = 0; nb < 8; nb++) {
        sh += g_part[0][nb][r];
        sf += g_part[1][nb][r];
    }

    __shared__ float red[SS];
    red[s] = sh; __syncthreads();
    for (int o = 256; o > 0; o >>= 1) { if (s < o) red[s] = fmaxf(red[s], red[s + o]); __syncthreads(); }
    float mh = red[0]; __syncthreads();
    float wh = expf(sh - mh);
    red[s] = wh; __syncthreads();
    for (int o = 256; o > 0; o >>= 1) { if (s < o) red[s] += red[s + o]; __syncthreads(); }
    wh = wh / (EPS + red[0]); __syncthreads();

    red[s] = sf; __syncthreads();
    for (int o = 256; o > 0; o >>= 1) { if (s < o) red[s] = fmaxf(red[s], red[s + o]); __syncthreads(); }
    float mf = red[0]; __syncthreads();
    float wf = expf(sf - mf);
    red[s] = wf; __syncthreads();
    for (int o = 256; o > 0; o >>= 1) { if (s < o) red[s] += red[s + o]; __syncthreads(); }
    wf = wf / (EPS + red[0]); __syncthreads();

    float p = wh * wf;
    red[s] = p; __syncthreads();
    for (int o = 256; o > 0; o >>= 1) { if (s < o) red[s] += red[s + o]; __syncthreads(); }
    float w = p / (EPS + red[0]);

    g_wbuf[r] = w;
    out[w_off + s * BB + b] = w;
}

// =====================================================================
// context partials: split s 4 ways
// =====================================================================
__global__ __launch_bounds__(128)
void context_kernel(const float* __restrict__ hid)
{
    const int b = blockIdx.y;
    const int d = blockIdx.x * 128 + threadIdx.x;
    const int s0 = blockIdx.z * 128;

    __shared__ float ws[128];
    ws[threadIdx.x] = g_wbuf[b * SS + s0 + threadIdx.x];
    __syncthreads();

    const float* base = hid + (size_t)b * SS * DD + (size_t)s0 * DD + d;
    float acc = 0.0f;
    #pragma unroll 8
    for (int s = 0; s < 128; s++)
        acc = fmaf(base[(size_t)s * DD], ws[s], acc);
    g_ctx_part[blockIdx.z][b * DD + d] = acc;
}

// =====================================================================
// final GEMM, K-split 4-way: grid (16, 4).
// =====================================================================
__global__ __launch_bounds__(256)
void final_part_kernel(const float* __restrict__ inp, const float* __restrict__ W3)
{
    const int colBase = blockIdx.x * 64;
    const int ky = blockIdx.y;
    const int kBeg = ky * 512;

    __shared__ float As[16][64];
    __shared__ float Bs[16][64];

    const int tid = threadIdx.x;
    const int tx = tid & 15;
    const int ty = tid >> 4;
    float acc[4][4] = {};

    for (int k0 = kBeg; k0 < kBeg + 512; k0 += 16) {
        #pragma unroll
        for (int i = tid; i < 64 * 16; i += 256) {
            int m = i >> 4, kk = i & 15;
            int k = k0 + kk;
            float a;
            if (k < DD) {
                int idx = m * DD + k;
                a = g_ctx_part[0][idx] + g_ctx_part[1][idx]
                  + g_ctx_part[2][idx] + g_ctx_part[3][idx];
            } else {
                a = inp[m * DD + (k - DD)];
            }
            As[kk][m] = a;
            Bs[kk][m] = W3[(size_t)(colBase + m) * (2 * DD) + k];
        }
        __syncthreads();
        #pragma unroll
        for (int kk = 0; kk < 16; kk++) {
            float a[4], w[4];
            #pragma unroll
            for (int i = 0; i < 4; i++) a[i] = As[kk][ty * 4 + i];
            #pragma unroll
            for (int j = 0; j < 4; j++) w[j] = Bs[kk][tx * 4 + j];
            #pragma unroll
            for (int i = 0; i < 4; i++)
                #pragma unroll
                for (int j = 0; j < 4; j++) acc[i][j] += a[i] * w[j];
        }
        __syncthreads();
    }
    #pragma unroll
    for (int i = 0; i < 4; i++) {
        int b = ty * 4 + i;
        #pragma unroll
        for (int j = 0; j < 4; j++) {
            int h = colBase + tx * 4 + j;
            g_fin_part[ky][b * HH + h] = acc[i][j];
        }
    }
}

// reduce partials + bias + finished mask. grid 256, block 256.
__global__ __launch_bounds__(256)
void final_reduce_kernel(const float* __restrict__ b3,
                         const unsigned char* __restrict__ fin,
                         float* __restrict__ out)
{
    int i = blockIdx.x * 256 + threadIdx.x;   // 0..65535
    int b = i >> 10;
    int h = i & 1023;
    float v = (g_fin_part[0][i] + g_fin_part[1][i])
            + (g_fin_part[2][i] + g_fin_part[3][i]) + b3[h];
    out[i] = fin[b] ? 0.0f : v;
}

// =====================================================================
// Host launcher (graph-capturable)
// =====================================================================
extern "C" void kernel_launch(void* const* d_in, const int* in_sizes, int n_in,
                              void* d_out, int out_size)
{
    const float* hidden = (const float*)d_in[0];
    const float* field  = (const float*)d_in[1];
    const float* input  = (const float*)d_in[2];
    const unsigned char* finished = (const unsigned char*)d_in[3];
    const float* W1 = (const float*)d_in[4];
    const float* b1 = (const float*)d_in[5];
    const float* W2 = (const float*)d_in[6];
    const float* b2 = (const float*)d_in[7];
    const float* W3 = (const float*)d_in[8];
    const float* b3 = (const float*)d_in[9];
    const float* W4 = (const float*)d_in[10];
    const float* b4 = (const float*)d_in[11];
    const float* W5 = (const float*)d_in[12];
    const float* b5 = (const float*)d_in[13];

    float* out = (float*)d_out;
    const int w_off = out_size - SS * BB;

    cudaFuncSetAttribute(score_mma_kernel,
                         cudaFuncAttributeMaxDynamicSharedMemorySize, SM_TOTAL);

    prep_all<<<dim3(4096, 3), 256>>>(hidden, field, W1, W4, input, W2, b2, W5, b5);
    score_mma_kernel<<<dim3(8, RT / 128, 2), 256, SM_TOTAL>>>(b1, b4);
    softmax_kernel<<<BB, SS>>>(out, w_off);
    context_kernel<<<dim3(DD / 128, BB, 4), 128>>>(hidden);
    final_part_kernel<<<dim3(HH / 64, 4), 256>>>(input, W3);
    final_reduce_kernel<<<256, 256>>>(b3, finished, out);
}

// round 14
// speedup vs baseline: 1.0289x; 1.0289x over previous
#include <cuda_runtime.h>
#include <cuda_bf16.h>
#include <cstdint>

// Problem dims
#define BB   64
#define SS   512
#define DD   1024
#define HH   1024
#define RT   (BB*SS)
#define EPS  1e-6f

// ---------------- device scratch (static; no runtime allocs) ----------------
__device__ __align__(16) __nv_bfloat16 g_xh[2][(size_t)RT * DD];
__device__ __align__(16) __nv_bfloat16 g_xl[2][(size_t)RT * DD];
__device__ __align__(16) __nv_bfloat16 g_wh[2][(size_t)HH * DD];
__device__ __align__(16) __nv_bfloat16 g_wl[2][(size_t)HH * DD];
__device__ float g_gamma[BB * HH];
__device__ float g_alpha[BB * HH];
__device__ float g_part[2][8][RT];
__device__ float g_wbuf[BB * SS];
__device__ float g_ctx_part[4][BB * DD];
__device__ float g_fin_part[4][BB * HH];

// =====================================================================
// FMA-only tanh (no MUFU); abs err ~3e-7.
// =====================================================================
__device__ __forceinline__ float tanh_fma(float x) {
    float ax = fabsf(x);
    float t  = fminf(ax * 2.885390081777927f, 30.0f);
    float k  = __fadd_rn(t, 12582912.0f);
    int   n  = __float_as_int(k) - 0x4B400000;
    float fn = __fadd_rn(k, -12582912.0f);
    float f  = __fadd_rn(t, -fn);
    float p = 1.5402387e-4f;
    p = fmaf(p, f, 1.3333558e-3f);
    p = fmaf(p, f, 9.6181291e-3f);
    p = fmaf(p, f, 5.5504109e-2f);
    p = fmaf(p, f, 2.4022651e-1f);
    p = fmaf(p, f, 6.9314718e-1f);
    p = fmaf(p, f, 1.0f);
    float E = p * __int_as_float(0x3f800000 + (n << 23));
    float d = E + 1.0f;
    float y = __int_as_float(0x7EF311C3 - __float_as_int(d));
    y = y * fmaf(-d, y, 2.0f);
    y = y * fmaf(-d, y, 2.0f);
    y = y * fmaf(-d, y, 2.0f);
    float r = fmaf(-2.0f, y, 1.0f);
    return copysignf(r, x);
}

// =====================================================================
// sm_80-portable PTX helpers
// =====================================================================
__device__ __forceinline__ uint32_t smem_u32(const void* p) {
    uint32_t a;
    asm("{ .reg .u64 t; cvta.to.shared.u64 t, %1; cvt.u32.u64 %0, t; }" : "=r"(a) : "l"(p));
    return a;
}
__device__ __forceinline__ void cp_async16(uint32_t dst, const void* src) {
    asm volatile("cp.async.cg.shared.global [%0], [%1], 16;" :: "r"(dst), "l"(src));
}
__device__ __forceinline__ void cp_commit() { asm volatile("cp.async.commit_group;" ::: "memory"); }
__device__ __forceinline__ void cp_wait1()  { asm volatile("cp.async.wait_group 1;" ::: "memory"); }

__device__ __forceinline__ void ldm_x4(uint32_t a, uint32_t& r0, uint32_t& r1,
                                       uint32_t& r2, uint32_t& r3) {
    asm volatile("ldmatrix.sync.aligned.m8n8.x4.shared.b16 {%0,%1,%2,%3}, [%4];"
                 : "=r"(r0), "=r"(r1), "=r"(r2), "=r"(r3) : "r"(a));
}
__device__ __forceinline__ void mma16816(float& c0, float& c1, float& c2, float& c3,
                                         uint32_t a0, uint32_t a1, uint32_t a2, uint32_t a3,
                                         uint32_t b0, uint32_t b1) {
    asm volatile("mma.sync.aligned.m16n8k16.row.col.f32.bf16.bf16.f32 "
                 "{%0,%1,%2,%3}, {%4,%5,%6,%7}, {%8,%9}, {%0,%1,%2,%3};"
                 : "+f"(c0), "+f"(c1), "+f"(c2), "+f"(c3)
                 : "r"(a0), "r"(a1), "r"(a2), "r"(a3), "r"(b0), "r"(b1));
}

// =====================================================================
// hi/lo split packer
// =====================================================================
__device__ __forceinline__ void split_pack(float4 v0, float4 v1, uint4& hp, uint4& lp) {
    __nv_bfloat16 h0 = __float2bfloat16(v0.x), h1 = __float2bfloat16(v0.y);
    __nv_bfloat16 h2 = __float2bfloat16(v0.z), h3 = __float2bfloat16(v0.w);
    __nv_bfloat16 h4 = __float2bfloat16(v1.x), h5 = __float2bfloat16(v1.y);
    __nv_bfloat16 h6 = __float2bfloat16(v1.z), h7 = __float2bfloat16(v1.w);
    __nv_bfloat16 l0 = __float2bfloat16(v0.x - __bfloat162float(h0));
    __nv_bfloat16 l1 = __float2bfloat16(v0.y - __bfloat162float(h1));
    __nv_bfloat16 l2 = __float2bfloat16(v0.z - __bfloat162float(h2));
    __nv_bfloat16 l3 = __float2bfloat16(v0.w - __bfloat162float(h3));
    __nv_bfloat16 l4 = __float2bfloat16(v1.x - __bfloat162float(h4));
    __nv_bfloat16 l5 = __float2bfloat16(v1.y - __bfloat162float(h5));
    __nv_bfloat16 l6 = __float2bfloat16(v1.z - __bfloat162float(h6));
    __nv_bfloat16 l7 = __float2bfloat16(v1.w - __bfloat162float(h7));
    hp.x = ((uint32_t)__bfloat16_as_ushort(h1) << 16) | __bfloat16_as_ushort(h0);
    hp.y = ((uint32_t)__bfloat16_as_ushort(h3) << 16) | __bfloat16_as_ushort(h2);
    hp.z = ((uint32_t)__bfloat16_as_ushort(h5) << 16) | __bfloat16_as_ushort(h4);
    hp.w = ((uint32_t)__bfloat16_as_ushort(h7) << 16) | __bfloat16_as_ushort(h6);
    lp.x = ((uint32_t)__bfloat16_as_ushort(l1) << 16) | __bfloat16_as_ushort(l0);
    lp.y = ((uint32_t)__bfloat16_as_ushort(l3) << 16) | __bfloat16_as_ushort(l2);
    lp.z = ((uint32_t)__bfloat16_as_ushort(l5) << 16) | __bfloat16_as_ushort(l4);
    lp.w = ((uint32_t)__bfloat16_as_ushort(l7) << 16) | __bfloat16_as_ushort(l6);
}

// X: 33.5M elts. grid 4096 x 256 threads, 4 iters x 8 elts (loads batched, MLP 8).
__global__ __launch_bounds__(256)
void cvt_x_kernel(const float* __restrict__ src, int z) {
    uint4* dh = reinterpret_cast<uint4*>(g_xh[z]);
    uint4* dl = reinterpret_cast<uint4*>(g_xl[z]);
    const float4* s4 = reinterpret_cast<const float4*>(src);
    float4 v[8];
    size_t base[4];
    #pragma unroll
    for (int it = 0; it < 4; ++it) {
        size_t g8 = (size_t)blockIdx.x * 1024 + it * 256 + threadIdx.x;
        base[it] = g8;
        v[it * 2]     = s4[g8 * 2];
        v[it * 2 + 1] = s4[g8 * 2 + 1];
    }
    #pragma unroll
    for (int it = 0; it < 4; ++it) {
        uint4 hp, lp;
        split_pack(v[it * 2], v[it * 2 + 1], hp, lp);
        dh[base[it]] = hp;
        dl[base[it]] = lp;
    }
}
// W: 1.05M elts. grid 128 x 256, 4 iters x 8 elts.
__global__ __launch_bounds__(256)
void cvt_w_kernel(const float* __restrict__ src, int z) {
    uint4* dh = reinterpret_cast<uint4*>(g_wh[z]);
    uint4* dl = reinterpret_cast<uint4*>(g_wl[z]);
    const float4* s4 = reinterpret_cast<const float4*>(src);
    #pragma unroll
    for (int it = 0; it < 4; ++it) {
        size_t g8 = (size_t)blockIdx.x * 1024 + it * 256 + threadIdx.x;
        float4 v0 = s4[g8 * 2];
        float4 v1 = s4[g8 * 2 + 1];
        uint4 hp, lp;
        split_pack(v0, v1, hp, lp);
        dh[g8] = hp;
        dl[g8] = lp;
    }
}

// =====================================================================
// Score GEMM — EXACT R4/R7/R11 structure (measured best: 1481.1 us total).
// mma.sync bf16 3-term split, CTA 128x128, kc=32, 2-stage cp.async,
// 8 warps m32xn64, ROWB=80. grid (8, 256, 2), block 256.
// =====================================================================
#define KCH        32
#define NCHUNK     (DD / KCH)             // 32
#define ROWB       80                      // 64B data + 16B pad
#define TILEB      (128 * ROWB)            // 10240
#define STAGEB     (4 * TILEB)             // 40960
#define SM_BIAS    (2 * STAGEB)            // 81920
#define SM_GAM     (SM_BIAS + 512)
#define SM_SPART   (SM_GAM + 512)
#define SM_TOTAL   (SM_SPART + 1024)       // 83968

__global__ __launch_bounds__(256)
void score_mma_kernel(const float* __restrict__ b1g, const float* __restrict__ b4g)
{
    extern __shared__ char sm[];
    const uint32_t sb = smem_u32(sm);

    const int z       = blockIdx.z;
    const int colBase = blockIdx.x * 128;
    const int rowBase = blockIdx.y * 128;
    const int tid     = threadIdx.x;
    const int lane    = tid & 31;
    const int wid     = tid >> 5;
    const int wm      = wid >> 1;         // 0..3
    const int wn      = wid & 1;          // 0..1

    const __nv_bfloat16* Ah = g_xh[z] + (size_t)rowBase * DD;
    const __nv_bfloat16* Al = g_xl[z] + (size_t)rowBase * DD;
    const __nv_bfloat16* Bh = g_wh[z] + (size_t)colBase * DD;
    const __nv_bfloat16* Bl = g_wl[z] + (size_t)colBase * DD;
    const float* bias = z ? b4g : b1g;
    const float* gm   = z ? g_alpha : g_gamma;
    const int b_idx   = rowBase / SS;

    float* sbias = reinterpret_cast<float*>(sm + SM_BIAS);
    float* sgam  = reinterpret_cast<float*>(sm + SM_GAM);
    float* spart = reinterpret_cast<float*>(sm + SM_SPART);   // [128][2]

    if (tid < 128) {
        sbias[tid] = bias[colBase + tid];
        sgam[tid]  = gm[b_idx * HH + colBase + tid];
    }

    // ---- cp.async stage loader: 4 tiles x 128 rows x 4 segs = 2048 x16B ----
    auto load_stage = [&](int ch, int buf) {
        const uint32_t sbase = sb + buf * STAGEB;
        const int kb = ch * KCH * 2;      // byte offset in bf16 row
        #pragma unroll
        for (int q = 0; q < 8; ++q) {
            int idx  = q * 256 + tid;     // 0..2047
            int tile = idx >> 9;          // /512
            int rem  = idx & 511;
            int row  = rem >> 2;
            int seg  = (rem & 3) << 4;    // 0,16,32,48
            const char* src;
            switch (tile) {
                case 0:  src = (const char*)(Ah + (size_t)row * DD) + kb + seg; break;
                case 1:  src = (const char*)(Al + (size_t)row * DD) + kb + seg; break;
                case 2:  src = (const char*)(Bh + (size_t)row * DD) + kb + seg; break;
                default: src = (const char*)(Bl + (size_t)row * DD) + kb + seg; break;
            }
            cp_async16(sbase + tile * TILEB + row * ROWB + seg, src);
        }
    };

    float c[2][8][4];
    #pragma unroll
    for (int mt = 0; mt < 2; ++mt)
        #pragma unroll
        for (int j = 0; j < 8; ++j)
            #pragma unroll
            for (int e = 0; e < 4; ++e) c[mt][j][e] = 0.0f;

    load_stage(0, 0); cp_commit();
    load_stage(1, 1); cp_commit();

    const int t4  = lane >> 3;            // ldmatrix tile select
    const int r8  = lane & 7;

    for (int ch = 0; ch < NCHUNK; ++ch) {
        cp_wait1();
        __syncthreads();
        const uint32_t sbase = sb + (ch & 1) * STAGEB;
        const uint32_t aHi = sbase;
        const uint32_t aLo = sbase + TILEB;
        const uint32_t bHi = sbase + 2 * TILEB;
        const uint32_t bLo = sbase + 3 * TILEB;

        #pragma unroll
        for (int ks = 0; ks < 2; ++ks) {
            const int koff = ks * 32 + ((t4 >> 1) << 4);    // A k-byte
            const int koffB = ks * 32 + ((t4 & 1) << 4);    // B k-byte
            uint32_t ah[2][4], al[2][4];
            #pragma unroll
            for (int mt = 0; mt < 2; ++mt) {
                const int row = wm * 32 + mt * 16 + r8 + ((t4 & 1) << 3);
                ldm_x4(aHi + row * ROWB + koff, ah[mt][0], ah[mt][1], ah[mt][2], ah[mt][3]);
                ldm_x4(aLo + row * ROWB + koff, al[mt][0], al[mt][1], al[mt][2], al[mt][3]);
            }
            uint32_t bh[8][2], bl[8][2];
            #pragma unroll
            for (int nt = 0; nt < 4; ++nt) {
                const int row = wn * 64 + nt * 16 + r8 + ((t4 >> 1) << 3);
                uint32_t r0, r1, r2, r3;
                ldm_x4(bHi + row * ROWB + koffB, r0, r1, r2, r3);
                bh[nt * 2][0] = r0; bh[nt * 2][1] = r1;
                bh[nt * 2 + 1][0] = r2; bh[nt * 2 + 1][1] = r3;
                ldm_x4(bLo + row * ROWB + koffB, r0, r1, r2, r3);
                bl[nt * 2][0] = r0; bl[nt * 2][1] = r1;
                bl[nt * 2 + 1][0] = r2; bl[nt * 2 + 1][1] = r3;
            }
            // term sweeps: 16 independent accums between same-acc reuses
            #pragma unroll
            for (int mt = 0; mt < 2; ++mt)
                #pragma unroll
                for (int j = 0; j < 8; ++j)
                    mma16816(c[mt][j][0], c[mt][j][1], c[mt][j][2], c[mt][j][3],
                             ah[mt][0], ah[mt][1], ah[mt][2], ah[mt][3],
                             bh[j][0], bh[j][1]);
            #pragma unroll
            for (int mt = 0; mt < 2; ++mt)
                #pragma unroll
                for (int j = 0; j < 8; ++j)
                    mma16816(c[mt][j][0], c[mt][j][1], c[mt][j][2], c[mt][j][3],
                             ah[mt][0], ah[mt][1], ah[mt][2], ah[mt][3],
                             bl[j][0], bl[j][1]);
            #pragma unroll
            for (int mt = 0; mt < 2; ++mt)
                #pragma unroll
                for (int j = 0; j < 8; ++j)
                    mma16816(c[mt][j][0], c[mt][j][1], c[mt][j][2], c[mt][j][3],
                             al[mt][0], al[mt][1], al[mt][2], al[mt][3],
                             bh[j][0], bh[j][1]);
        }
        __syncthreads();
        if (ch + 2 < NCHUNK) load_stage(ch + 2, ch & 1);
        cp_commit();
    }

    // ---- epilogue: tanh + dot(gamma), reduce to per-row score partials ----
    float rsum[2][2] = {};
    #pragma unroll
    for (int mt = 0; mt < 2; ++mt) {
        #pragma unroll
        for (int j = 0; j < 8; ++j) {
            const int col0 = wn * 64 + j * 8 + (lane & 3) * 2;
            float b0 = sbias[col0], b1v = sbias[col0 + 1];
            float g0 = sgam[col0],  g1v = sgam[col0 + 1];
            rsum[mt][0] = fmaf(tanh_fma(c[mt][j][0] + b0), g0, rsum[mt][0]);
            rsum[mt][0] = fmaf(tanh_fma(c[mt][j][1] + b1v), g1v, rsum[mt][0]);
            rsum[mt][1] = fmaf(tanh_fma(c[mt][j][2] + b0), g0, rsum[mt][1]);
            rsum[mt][1] = fmaf(tanh_fma(c[mt][j][3] + b1v), g1v, rsum[mt][1]);
        }
    }
    #pragma unroll
    for (int mt = 0; mt < 2; ++mt)
        #pragma unroll
        for (int h = 0; h < 2; ++h) {
            float v = rsum[mt][h];
            v += __shfl_xor_sync(0xffffffffu, v, 1);
            v += __shfl_xor_sync(0xffffffffu, v, 2);
            rsum[mt][h] = v;
        }
    if ((lane & 3) == 0) {
        #pragma unroll
        for (int mt = 0; mt < 2; ++mt)
            #pragma unroll
            for (int h = 0; h < 2; ++h) {
                int r = wm * 32 + mt * 16 + (lane >> 2) + h * 8;
                spart[r * 2 + wn] = rsum[mt][h];
            }
    }
    __syncthreads();
    if (tid < 128)
        g_part[z][blockIdx.x][rowBase + tid] = spart[tid * 2] + spart[tid * 2 + 1];
}

// =====================================================================
// gamma/alpha
// =====================================================================
__global__ __launch_bounds__(256)
void gamma_alpha_kernel(const float* __restrict__ inp,
                        const float* __restrict__ W2, const float* __restrict__ b2,
                        const float* __restrict__ W5, const float* __restrict__ b5)
{
    const int z = blockIdx.y;
    const float* W    = z ? W5 : W2;
    const float* bias = z ? b5 : b2;
    float* out        = z ? g_alpha : g_gamma;

    const int colBase = blockIdx.x * 64;
    __shared__ float As[16][64];
    __shared__ float Bs[16][64];

    const int tid = threadIdx.x;
    const int tx = tid & 15;
    const int ty = tid >> 4;
    float acc[4][4] = {};

    for (int k0 = 0; k0 < DD; k0 += 16) {
        #pragma unroll
        for (int i = tid; i < 64 * 16; i += 256) {
            int m = i >> 4, kk = i & 15;
            As[kk][m] = inp[m * DD + k0 + kk];
            Bs[kk][m] = W[(colBase + m) * DD + k0 + kk];
        }
        __syncthreads();
        #pragma unroll
        for (int kk = 0; kk < 16; kk++) {
            float a[4], w[4];
            #pragma unroll
            for (int i = 0; i < 4; i++) a[i] = As[kk][ty * 4 + i];
            #pragma unroll
            for (int j = 0; j < 4; j++) w[j] = Bs[kk][tx * 4 + j];
            #pragma unroll
            for (int i = 0; i < 4; i++)
                #pragma unroll
                for (int j = 0; j < 4; j++) acc[i][j] += a[i] * w[j];
        }
        __syncthreads();
    }
    #pragma unroll
    for (int i = 0; i < 4; i++) {
        int b = ty * 4 + i;
        #pragma unroll
        for (int j = 0; j < 4; j++) {
            int h = colBase + tx * 4 + j;
            out[b * HH + h] = tanh_fma(acc[i][j] + bias[h]);
        }
    }
}

// =====================================================================
// softmax combine (exact reference semantics)
// =====================================================================
__global__ __launch_bounds__(512)
void softmax_kernel(float* __restrict__ out, int w_off)
{
    const int b = blockIdx.x;
    const int s = threadIdx.x;
    const int r = b * SS + s;

    float sh = 0.0f, sf = 0.0f;
    #pragma unroll
    for (int nb = 0; nb < 8; nb++) {
        sh += g_part[0][nb][r];
        sf += g_part[1][nb][r];
    }

    __shared__ float red[SS];
    red[s] = sh; __syncthreads();
    for (int o = 256; o > 0; o >>= 1) { if (s < o) red[s] = fmaxf(red[s], red[s + o]); __syncthreads(); }
    float mh = red[0]; __syncthreads();
    float wh = expf(sh - mh);
    red[s] = wh; __syncthreads();
    for (int o = 256; o > 0; o >>= 1) { if (s < o) red[s] += red[s + o]; __syncthreads(); }
    wh = wh / (EPS + red[0]); __syncthreads();

    red[s] = sf; __syncthreads();
    for (int o = 256; o > 0; o >>= 1) { if (s < o) red[s] = fmaxf(red[s], red[s + o]); __syncthreads(); }
    float mf = red[0]; __syncthreads();
    float wf = expf(sf - mf);
    red[s] = wf; __syncthreads();
    for (int o = 256; o > 0; o >>= 1) { if (s < o) red[s] += red[s + o]; __syncthreads(); }
    wf = wf / (EPS + red[0]); __syncthreads();

    float p = wh * wf;
    red[s] = p; __syncthreads();
    for (int o = 256; o > 0; o >>= 1) { if (s < o) red[s] += red[s + o]; __syncthreads(); }
    float w = p / (EPS + red[0]);

    g_wbuf[r] = w;
    out[w_off + s * BB + b] = w;
}

// =====================================================================
// context partials: split s 4 ways
// =====================================================================
__global__ __launch_bounds__(128)
void context_kernel(const float* __restrict__ hid)
{
    const int b = blockIdx.y;
    const int d = blockIdx.x * 128 + threadIdx.x;
    const int s0 = blockIdx.z * 128;

    __shared__ float ws[128];
    ws[threadIdx.x] = g_wbuf[b * SS + s0 + threadIdx.x];
    __syncthreads();

    const float* base = hid + (size_t)b * SS * DD + (size_t)s0 * DD + d;
    float acc = 0.0f;
    #pragma unroll 8
    for (int s = 0; s < 128; s++)
        acc = fmaf(base[(size_t)s * DD], ws[s], acc);
    g_ctx_part[blockIdx.z][b * DD + d] = acc;
}

// =====================================================================
// final GEMM, K-split 4-way: grid (16, 4).
// =====================================================================
__global__ __launch_bounds__(256)
void final_part_kernel(const float* __restrict__ inp, const float* __restrict__ W3)
{
    const int colBase = blockIdx.x * 64;
    const int ky = blockIdx.y;
    const int kBeg = ky * 512;

    __shared__ float As[16][64];
    __shared__ float Bs[16][64];

    const int tid = threadIdx.x;
    const int tx = tid & 15;
    const int ty = tid >> 4;
    float acc[4][4] = {};

    for (int k0 = kBeg; k0 < kBeg + 512; k0 += 16) {
        #pragma unroll
        for (int i = tid; i < 64 * 16; i += 256) {
            int m = i >> 4, kk = i & 15;
            int k = k0 + kk;
            float a;
            if (k < DD) {
                int idx = m * DD + k;
                a = g_ctx_part[0][idx] + g_ctx_part[1][idx]
                  + g_ctx_part[2][idx] + g_ctx_part[3][idx];
            } else {
                a = inp[m * DD + (k - DD)];
            }
            As[kk][m] = a;
            Bs[kk][m] = W3[(size_t)(colBase + m) * (2 * DD) + k];
        }
        __syncthreads();
        #pragma unroll
        for (int kk = 0; kk < 16; kk++) {
            float a[4], w[4];
            #pragma unroll
            for (int i = 0; i < 4; i++) a[i] = As[kk][ty * 4 + i];
            #pragma unroll
            for (int j = 0; j < 4; j++) w[j] = Bs[kk][tx * 4 + j];
            #pragma unroll
            for (int i = 0; i < 4; i++)
                #pragma unroll
                for (int j = 0; j < 4; j++) acc[i][j] += a[i] * w[j];
        }
        __syncthreads();
    }
    #pragma unroll
    for (int i = 0; i < 4; i++) {
        int b = ty * 4 + i;
        #pragma unroll
        for (int j = 0; j < 4; j++) {
            int h = colBase + tx * 4 + j;
            g_fin_part[ky][b * HH + h] = acc[i][j];
        }
    }
}

// reduce partials + bias + finished mask. grid 256, block 256.
__global__ __launch_bounds__(256)
void final_reduce_kernel(const float* __restrict__ b3,
                         const unsigned char* __restrict__ fin,
                         float* __restrict__ out)
{
    int i = blockIdx.x * 256 + threadIdx.x;   // 0..65535
    int b = i >> 10;
    int h = i & 1023;
    float v = (g_fin_part[0][i] + g_fin_part[1][i])
            + (g_fin_part[2][i] + g_fin_part[3][i]) + b3[h];
    out[i] = fin[b] ? 0.0f : v;
}

// =====================================================================
// Host launcher (graph-capturable)
// =====================================================================
extern "C" void kernel_launch(void* const* d_in, const int* in_sizes, int n_in,
                              void* d_out, int out_size)
{
    const float* hidden = (const float*)d_in[0];
    const float* field  = (const float*)d_in[1];
    const float* input  = (const float*)d_in[2];
    const unsigned char* finished = (const unsigned char*)d_in[3];
    const float* W1 = (const float*)d_in[4];
    const float* b1 = (const float*)d_in[5];
    const float* W2 = (const float*)d_in[6];
    const float* b2 = (const float*)d_in[7];
    const float* W3 = (const float*)d_in[8];
    const float* b3 = (const float*)d_in[9];
    const float* W4 = (const float*)d_in[10];
    const float* b4 = (const float*)d_in[11];
    const float* W5 = (const float*)d_in[12];
    const float* b5 = (const float*)d_in[13];

    float* out = (float*)d_out;
    const int w_off = out_size - SS * BB;

    cudaFuncSetAttribute(score_mma_kernel,
                         cudaFuncAttributeMaxDynamicSharedMemorySize, SM_TOTAL);

    cvt_x_kernel<<<4096, 256>>>(hidden, 0);
    cvt_x_kernel<<<4096, 256>>>(field, 1);
    cvt_w_kernel<<<128, 256>>>(W1, 0);
    cvt_w_kernel<<<128, 256>>>(W4, 1);
    gamma_alpha_kernel<<<dim3(HH / 64, 2), 256>>>(input, W2, b2, W5, b5);
    score_mma_kernel<<<dim3(8, RT / 128, 2), 256, SM_TOTAL>>>(b1, b4);
    softmax_kernel<<<BB, SS>>>(out, w_off);
    context_kernel<<<dim3(DD / 128, BB, 4), 128>>>(hidden);
    final_part_kernel<<<dim3(HH / 64, 4), 256>>>(input, W3);
    final_reduce_kernel<<<256, 256>>>(b3, finished, out);
}

// round 15
// speedup vs baseline: 1.0848x; 1.0543x over previous
#include <cuda_runtime.h>
#include <cuda_bf16.h>
#include <cstdint>

// Problem dims
#define BB   64
#define SS   512
#define DD   1024
#define HH   1024
#define RT   (BB*SS)
#define EPS  1e-6f

// ---------------- device scratch (static; no runtime allocs) ----------------
__device__ __align__(16) __nv_bfloat16 g_xh[2][(size_t)RT * DD];
__device__ __align__(16) __nv_bfloat16 g_xl[2][(size_t)RT * DD];
__device__ __align__(16) __nv_bfloat16 g_wh[2][(size_t)HH * DD];
__device__ __align__(16) __nv_bfloat16 g_wl[2][(size_t)HH * DD];
__device__ float g_gamma[BB * HH];
__device__ float g_alpha[BB * HH];
__device__ float g_ga_part[4][2][BB * HH];   // gamma/alpha K-split partials
__device__ float g_part[2][8][RT];
__device__ float g_wbuf[BB * SS];
__device__ float g_ctx_part[4][BB * DD];
__device__ float g_fin_part[4][BB * HH];

// =====================================================================
// FMA-only tanh (no MUFU); abs err ~3e-7.
// =====================================================================
__device__ __forceinline__ float tanh_fma(float x) {
    float ax = fabsf(x);
    float t  = fminf(ax * 2.885390081777927f, 30.0f);
    float k  = __fadd_rn(t, 12582912.0f);
    int   n  = __float_as_int(k) - 0x4B400000;
    float fn = __fadd_rn(k, -12582912.0f);
    float f  = __fadd_rn(t, -fn);
    float p = 1.5402387e-4f;
    p = fmaf(p, f, 1.3333558e-3f);
    p = fmaf(p, f, 9.6181291e-3f);
    p = fmaf(p, f, 5.5504109e-2f);
    p = fmaf(p, f, 2.4022651e-1f);
    p = fmaf(p, f, 6.9314718e-1f);
    p = fmaf(p, f, 1.0f);
    float E = p * __int_as_float(0x3f800000 + (n << 23));
    float d = E + 1.0f;
    float y = __int_as_float(0x7EF311C3 - __float_as_int(d));
    y = y * fmaf(-d, y, 2.0f);
    y = y * fmaf(-d, y, 2.0f);
    y = y * fmaf(-d, y, 2.0f);
    float r = fmaf(-2.0f, y, 1.0f);
    return copysignf(r, x);
}

// =====================================================================
// sm_80-portable PTX helpers
// =====================================================================
__device__ __forceinline__ uint32_t smem_u32(const void* p) {
    uint32_t a;
    asm("{ .reg .u64 t; cvta.to.shared.u64 t, %1; cvt.u32.u64 %0, t; }" : "=r"(a) : "l"(p));
    return a;
}
__device__ __forceinline__ void cp_async16(uint32_t dst, const void* src) {
    asm volatile("cp.async.cg.shared.global [%0], [%1], 16;" :: "r"(dst), "l"(src));
}
__device__ __forceinline__ void cp_commit() { asm volatile("cp.async.commit_group;" ::: "memory"); }
__device__ __forceinline__ void cp_wait1()  { asm volatile("cp.async.wait_group 1;" ::: "memory"); }

__device__ __forceinline__ void ldm_x4(uint32_t a, uint32_t& r0, uint32_t& r1,
                                       uint32_t& r2, uint32_t& r3) {
    asm volatile("ldmatrix.sync.aligned.m8n8.x4.shared.b16 {%0,%1,%2,%3}, [%4];"
                 : "=r"(r0), "=r"(r1), "=r"(r2), "=r"(r3) : "r"(a));
}
__device__ __forceinline__ void mma16816(float& c0, float& c1, float& c2, float& c3,
                                         uint32_t a0, uint32_t a1, uint32_t a2, uint32_t a3,
                                         uint32_t b0, uint32_t b1) {
    asm volatile("mma.sync.aligned.m16n8k16.row.col.f32.bf16.bf16.f32 "
                 "{%0,%1,%2,%3}, {%4,%5,%6,%7}, {%8,%9}, {%0,%1,%2,%3};"
                 : "+f"(c0), "+f"(c1), "+f"(c2), "+f"(c3)
                 : "r"(a0), "r"(a1), "r"(a2), "r"(a3), "r"(b0), "r"(b1));
}

// =====================================================================
// hi/lo split packer
// =====================================================================
__device__ __forceinline__ void split_pack(float4 v0, float4 v1, uint4& hp, uint4& lp) {
    __nv_bfloat16 h0 = __float2bfloat16(v0.x), h1 = __float2bfloat16(v0.y);
    __nv_bfloat16 h2 = __float2bfloat16(v0.z), h3 = __float2bfloat16(v0.w);
    __nv_bfloat16 h4 = __float2bfloat16(v1.x), h5 = __float2bfloat16(v1.y);
    __nv_bfloat16 h6 = __float2bfloat16(v1.z), h7 = __float2bfloat16(v1.w);
    __nv_bfloat16 l0 = __float2bfloat16(v0.x - __bfloat162float(h0));
    __nv_bfloat16 l1 = __float2bfloat16(v0.y - __bfloat162float(h1));
    __nv_bfloat16 l2 = __float2bfloat16(v0.z - __bfloat162float(h2));
    __nv_bfloat16 l3 = __float2bfloat16(v0.w - __bfloat162float(h3));
    __nv_bfloat16 l4 = __float2bfloat16(v1.x - __bfloat162float(h4));
    __nv_bfloat16 l5 = __float2bfloat16(v1.y - __bfloat162float(h5));
    __nv_bfloat16 l6 = __float2bfloat16(v1.z - __bfloat162float(h6));
    __nv_bfloat16 l7 = __float2bfloat16(v1.w - __bfloat162float(h7));
    hp.x = ((uint32_t)__bfloat16_as_ushort(h1) << 16) | __bfloat16_as_ushort(h0);
    hp.y = ((uint32_t)__bfloat16_as_ushort(h3) << 16) | __bfloat16_as_ushort(h2);
    hp.z = ((uint32_t)__bfloat16_as_ushort(h5) << 16) | __bfloat16_as_ushort(h4);
    hp.w = ((uint32_t)__bfloat16_as_ushort(h7) << 16) | __bfloat16_as_ushort(h6);
    lp.x = ((uint32_t)__bfloat16_as_ushort(l1) << 16) | __bfloat16_as_ushort(l0);
    lp.y = ((uint32_t)__bfloat16_as_ushort(l3) << 16) | __bfloat16_as_ushort(l2);
    lp.z = ((uint32_t)__bfloat16_as_ushort(l5) << 16) | __bfloat16_as_ushort(l4);
    lp.w = ((uint32_t)__bfloat16_as_ushort(l7) << 16) | __bfloat16_as_ushort(l6);
}

// X convert, both z fused (homogeneous body): grid (4096, 2), block 256.
__global__ __launch_bounds__(256)
void cvt_x_kernel(const float* __restrict__ hidden, const float* __restrict__ field) {
    const int z = blockIdx.y;
    const float* src = z ? field : hidden;
    uint4* dh = reinterpret_cast<uint4*>(g_xh[z]);
    uint4* dl = reinterpret_cast<uint4*>(g_xl[z]);
    const float4* s4 = reinterpret_cast<const float4*>(src);
    float4 v[8];
    size_t base[4];
    #pragma unroll
    for (int it = 0; it < 4; ++it) {
        size_t g8 = (size_t)blockIdx.x * 1024 + it * 256 + threadIdx.x;
        base[it] = g8;
        v[it * 2]     = s4[g8 * 2];
        v[it * 2 + 1] = s4[g8 * 2 + 1];
    }
    #pragma unroll
    for (int it = 0; it < 4; ++it) {
        uint4 hp, lp;
        split_pack(v[it * 2], v[it * 2 + 1], hp, lp);
        dh[base[it]] = hp;
        dl[base[it]] = lp;
    }
}
// W convert, both z fused: grid (128, 2), block 256.
__global__ __launch_bounds__(256)
void cvt_w_kernel(const float* __restrict__ W1g, const float* __restrict__ W4g) {
    const int z = blockIdx.y;
    const float* src = z ? W4g : W1g;
    uint4* dh = reinterpret_cast<uint4*>(g_wh[z]);
    uint4* dl = reinterpret_cast<uint4*>(g_wl[z]);
    const float4* s4 = reinterpret_cast<const float4*>(src);
    #pragma unroll
    for (int it = 0; it < 4; ++it) {
        size_t g8 = (size_t)blockIdx.x * 1024 + it * 256 + threadIdx.x;
        float4 v0 = s4[g8 * 2];
        float4 v1 = s4[g8 * 2 + 1];
        uint4 hp, lp;
        split_pack(v0, v1, hp, lp);
        dh[g8] = hp;
        dl[g8] = lp;
    }
}

// =====================================================================
// gamma/alpha GEMM, K-split 4-way: grid (16, 2, 4), block 256.
// partial[ky][z][b,h] over K range ky*256..+256; no tanh/bias here.
// =====================================================================
__global__ __launch_bounds__(256)
void gamma_part_kernel(const float* __restrict__ inp,
                       const float* __restrict__ W2, const float* __restrict__ W5)
{
    const int z  = blockIdx.y;
    const int ky = blockIdx.z;
    const float* W = z ? W5 : W2;
    float* out = g_ga_part[ky][z];

    const int colBase = blockIdx.x * 64;
    const int kBeg = ky * 256;
    __shared__ float As[16][64];
    __shared__ float Bs[16][64];

    const int tid = threadIdx.x;
    const int tx = tid & 15;
    const int ty = tid >> 4;
    float acc[4][4] = {};

    for (int k0 = kBeg; k0 < kBeg + 256; k0 += 16) {
        #pragma unroll
        for (int i = tid; i < 64 * 16; i += 256) {
            int m = i >> 4, kk = i & 15;
            As[kk][m] = inp[m * DD + k0 + kk];
            Bs[kk][m] = W[(colBase + m) * DD + k0 + kk];
        }
        __syncthreads();
        #pragma unroll
        for (int kk = 0; kk < 16; kk++) {
            float a[4], w[4];
            #pragma unroll
            for (int i = 0; i < 4; i++) a[i] = As[kk][ty * 4 + i];
            #pragma unroll
            for (int j = 0; j < 4; j++) w[j] = Bs[kk][tx * 4 + j];
            #pragma unroll
            for (int i = 0; i < 4; i++)
                #pragma unroll
                for (int j = 0; j < 4; j++) acc[i][j] += a[i] * w[j];
        }
        __syncthreads();
    }
    #pragma unroll
    for (int i = 0; i < 4; i++) {
        int b = ty * 4 + i;
        #pragma unroll
        for (int j = 0; j < 4; j++) {
            int h = colBase + tx * 4 + j;
            out[b * HH + h] = acc[i][j];
        }
    }
}

// reduce gamma/alpha partials + bias + tanh. grid (128, 2), block 512.
__global__ __launch_bounds__(512)
void gamma_reduce_kernel(const float* __restrict__ b2, const float* __restrict__ b5)
{
    const int z = blockIdx.y;
    const float* bias = z ? b5 : b2;
    float* out = z ? g_alpha : g_gamma;
    int i = blockIdx.x * 512 + threadIdx.x;    // 0..65535
    int h = i & 1023;
    float v = (g_ga_part[0][z][i] + g_ga_part[1][z][i])
            + (g_ga_part[2][z][i] + g_ga_part[3][z][i]) + bias[h];
    out[i] = tanh_fma(v);
}

// =====================================================================
// Score GEMM — EXACT R11/R14 structure (measured best: 1479.1 us total).
// mma.sync bf16 3-term split, CTA 128x128, kc=32, 2-stage cp.async,
// 8 warps m32xn64, ROWB=80. grid (8, 256, 2), block 256.
// =====================================================================
#define KCH        32
#define NCHUNK     (DD / KCH)             // 32
#define ROWB       80                      // 64B data + 16B pad
#define TILEB      (128 * ROWB)            // 10240
#define STAGEB     (4 * TILEB)             // 40960
#define SM_BIAS    (2 * STAGEB)            // 81920
#define SM_GAM     (SM_BIAS + 512)
#define SM_SPART   (SM_GAM + 512)
#define SM_TOTAL   (SM_SPART + 1024)       // 83968

__global__ __launch_bounds__(256)
void score_mma_kernel(const float* __restrict__ b1g, const float* __restrict__ b4g)
{
    extern __shared__ char sm[];
    const uint32_t sb = smem_u32(sm);

    const int z       = blockIdx.z;
    const int colBase = blockIdx.x * 128;
    const int rowBase = blockIdx.y * 128;
    const int tid     = threadIdx.x;
    const int lane    = tid & 31;
    const int wid     = tid >> 5;
    const int wm      = wid >> 1;         // 0..3
    const int wn      = wid & 1;          // 0..1

    const __nv_bfloat16* Ah = g_xh[z] + (size_t)rowBase * DD;
    const __nv_bfloat16* Al = g_xl[z] + (size_t)rowBase * DD;
    const __nv_bfloat16* Bh = g_wh[z] + (size_t)colBase * DD;
    const __nv_bfloat16* Bl = g_wl[z] + (size_t)colBase * DD;
    const float* bias = z ? b4g : b1g;
    const float* gm   = z ? g_alpha : g_gamma;
    const int b_idx   = rowBase / SS;

    float* sbias = reinterpret_cast<float*>(sm + SM_BIAS);
    float* sgam  = reinterpret_cast<float*>(sm + SM_GAM);
    float* spart = reinterpret_cast<float*>(sm + SM_SPART);   // [128][2]

    if (tid < 128) {
        sbias[tid] = bias[colBase + tid];
        sgam[tid]  = gm[b_idx * HH + colBase + tid];
    }

    // ---- cp.async stage loader: 4 tiles x 128 rows x 4 segs = 2048 x16B ----
    auto load_stage = [&](int ch, int buf) {
        const uint32_t sbase = sb + buf * STAGEB;
        const int kb = ch * KCH * 2;      // byte offset in bf16 row
        #pragma unroll
        for (int q = 0; q < 8; ++q) {
            int idx  = q * 256 + tid;     // 0..2047
            int tile = idx >> 9;          // /512
            int rem  = idx & 511;
            int row  = rem >> 2;
            int seg  = (rem & 3) << 4;    // 0,16,32,48
            const char* src;
            switch (tile) {
                case 0:  src = (const char*)(Ah + (size_t)row * DD) + kb + seg; break;
                case 1:  src = (const char*)(Al + (size_t)row * DD) + kb + seg; break;
                case 2:  src = (const char*)(Bh + (size_t)row * DD) + kb + seg; break;
                default: src = (const char*)(Bl + (size_t)row * DD) + kb + seg; break;
            }
            cp_async16(sbase + tile * TILEB + row * ROWB + seg, src);
        }
    };

    float c[2][8][4];
    #pragma unroll
    for (int mt = 0; mt < 2; ++mt)
        #pragma unroll
        for (int j = 0; j < 8; ++j)
            #pragma unroll
            for (int e = 0; e < 4; ++e) c[mt][j][e] = 0.0f;

    load_stage(0, 0); cp_commit();
    load_stage(1, 1); cp_commit();

    const int t4  = lane >> 3;            // ldmatrix tile select
    const int r8  = lane & 7;

    for (int ch = 0; ch < NCHUNK; ++ch) {
        cp_wait1();
        __syncthreads();
        const uint32_t sbase = sb + (ch & 1) * STAGEB;
        const uint32_t aHi = sbase;
        const uint32_t aLo = sbase + TILEB;
        const uint32_t bHi = sbase + 2 * TILEB;
        const uint32_t bLo = sbase + 3 * TILEB;

        #pragma unroll
        for (int ks = 0; ks < 2; ++ks) {
            const int koff = ks * 32 + ((t4 >> 1) << 4);    // A k-byte
            const int koffB = ks * 32 + ((t4 & 1) << 4);    // B k-byte
            uint32_t ah[2][4], al[2][4];
            #pragma unroll
            for (int mt = 0; mt < 2; ++mt) {
                const int row = wm * 32 + mt * 16 + r8 + ((t4 & 1) << 3);
                ldm_x4(aHi + row * ROWB + koff, ah[mt][0], ah[mt][1], ah[mt][2], ah[mt][3]);
                ldm_x4(aLo + row * ROWB + koff, al[mt][0], al[mt][1], al[mt][2], al[mt][3]);
            }
            uint32_t bh[8][2], bl[8][2];
            #pragma unroll
            for (int nt = 0; nt < 4; ++nt) {
                const int row = wn * 64 + nt * 16 + r8 + ((t4 >> 1) << 3);
                uint32_t r0, r1, r2, r3;
                ldm_x4(bHi + row * ROWB + koffB, r0, r1, r2, r3);
                bh[nt * 2][0] = r0; bh[nt * 2][1] = r1;
                bh[nt * 2 + 1][0] = r2; bh[nt * 2 + 1][1] = r3;
                ldm_x4(bLo + row * ROWB + koffB, r0, r1, r2, r3);
                bl[nt * 2][0] = r0; bl[nt * 2][1] = r1;
                bl[nt * 2 + 1][0] = r2; bl[nt * 2 + 1][1] = r3;
            }
            // term sweeps: 16 independent accums between same-acc reuses
            #pragma unroll
            for (int mt = 0; mt < 2; ++mt)
                #pragma unroll
                for (int j = 0; j < 8; ++j)
                    mma16816(c[mt][j][0], c[mt][j][1], c[mt][j][2], c[mt][j][3],
                             ah[mt][0], ah[mt][1], ah[mt][2], ah[mt][3],
                             bh[j][0], bh[j][1]);
            #pragma unroll
            for (int mt = 0; mt < 2; ++mt)
                #pragma unroll
                for (int j = 0; j < 8; ++j)
                    mma16816(c[mt][j][0], c[mt][j][1], c[mt][j][2], c[mt][j][3],
                             ah[mt][0], ah[mt][1], ah[mt][2], ah[mt][3],
                             bl[j][0], bl[j][1]);
            #pragma unroll
            for (int mt = 0; mt < 2; ++mt)
                #pragma unroll
                for (int j = 0; j < 8; ++j)
                    mma16816(c[mt][j][0], c[mt][j][1], c[mt][j][2], c[mt][j][3],
                             al[mt][0], al[mt][1], al[mt][2], al[mt][3],
                             bh[j][0], bh[j][1]);
        }
        __syncthreads();
        if (ch + 2 < NCHUNK) load_stage(ch + 2, ch & 1);
        cp_commit();
    }

    // ---- epilogue: tanh + dot(gamma), reduce to per-row score partials ----
    float rsum[2][2] = {};
    #pragma unroll
    for (int mt = 0; mt < 2; ++mt) {
        #pragma unroll
        for (int j = 0; j < 8; ++j) {
            const int col0 = wn * 64 + j * 8 + (lane & 3) * 2;
            float b0 = sbias[col0], b1v = sbias[col0 + 1];
            float g0 = sgam[col0],  g1v = sgam[col0 + 1];
            rsum[mt][0] = fmaf(tanh_fma(c[mt][j][0] + b0), g0, rsum[mt][0]);
            rsum[mt][0] = fmaf(tanh_fma(c[mt][j][1] + b1v), g1v, rsum[mt][0]);
            rsum[mt][1] = fmaf(tanh_fma(c[mt][j][2] + b0), g0, rsum[mt][1]);
            rsum[mt][1] = fmaf(tanh_fma(c[mt][j][3] + b1v), g1v, rsum[mt][1]);
        }
    }
    #pragma unroll
    for (int mt = 0; mt < 2; ++mt)
        #pragma unroll
        for (int h = 0; h < 2; ++h) {
            float v = rsum[mt][h];
            v += __shfl_xor_sync(0xffffffffu, v, 1);
            v += __shfl_xor_sync(0xffffffffu, v, 2);
            rsum[mt][h] = v;
        }
    if ((lane & 3) == 0) {
        #pragma unroll
        for (int mt = 0; mt < 2; ++mt)
            #pragma unroll
            for (int h = 0; h < 2; ++h) {
                int r = wm * 32 + mt * 16 + (lane >> 2) + h * 8;
                spart[r * 2 + wn] = rsum[mt][h];
            }
    }
    __syncthreads();
    if (tid < 128)
        g_part[z][blockIdx.x][rowBase + tid] = spart[tid * 2] + spart[tid * 2 + 1];
}

// =====================================================================
// softmax combine (exact reference semantics)
// =====================================================================
__global__ __launch_bounds__(512)
void softmax_kernel(float* __restrict__ out, int w_off)
{
    const int b = blockIdx.x;
    const int s = threadIdx.x;
    const int r = b * SS + s;

    float sh = 0.0f, sf = 0.0f;
    #pragma unroll
    for (int nb = 0; nb < 8; nb++) {
        sh += g_part[0][nb][r];
        sf += g_part[1][nb][r];
    }

    __shared__ float red[SS];
    red[s] = sh; __syncthreads();
    for (int o = 256; o > 0; o >>= 1) { if (s < o) red[s] = fmaxf(red[s], red[s + o]); __syncthreads(); }
    float mh = red[0]; __syncthreads();
    float wh = expf(sh - mh);
    red[s] = wh; __syncthreads();
    for (int o = 256; o > 0; o >>= 1) { if (s < o) red[s] += red[s + o]; __syncthreads(); }
    wh = wh / (EPS + red[0]); __syncthreads();

    red[s] = sf; __syncthreads();
    for (int o = 256; o > 0; o >>= 1) { if (s < o) red[s] = fmaxf(red[s], red[s + o]); __syncthreads(); }
    float mf = red[0]; __syncthreads();
    float wf = expf(sf - mf);
    red[s] = wf; __syncthreads();
    for (int o = 256; o > 0; o >>= 1) { if (s < o) red[s] += red[s + o]; __syncthreads(); }
    wf = wf / (EPS + red[0]); __syncthreads();

    float p = wh * wf;
    red[s] = p; __syncthreads();
    for (int o = 256; o > 0; o >>= 1) { if (s < o) red[s] += red[s + o]; __syncthreads(); }
    float w = p / (EPS + red[0]);

    g_wbuf[r] = w;
    out[w_off + s * BB + b] = w;
}

// =====================================================================
// context partials: split s 4 ways
// =====================================================================
__global__ __launch_bounds__(128)
void context_kernel(const float* __restrict__ hid)
{
    const int b = blockIdx.y;
    const int d = blockIdx.x * 128 + threadIdx.x;
    const int s0 = blockIdx.z * 128;

    __shared__ float ws[128];
    ws[threadIdx.x] = g_wbuf[b * SS + s0 + threadIdx.x];
    __syncthreads();

    const float* base = hid + (size_t)b * SS * DD + (size_t)s0 * DD + d;
    float acc = 0.0f;
    #pragma unroll 8
    for (int s = 0; s < 128; s++)
        acc = fmaf(base[(size_t)s * DD], ws[s], acc);
    g_ctx_part[blockIdx.z][b * DD + d] = acc;
}

// =====================================================================
// final GEMM, K-split 4-way: grid (16, 4).
// =====================================================================
__global__ __launch_bounds__(256)
void final_part_kernel(const float* __restrict__ inp, const float* __restrict__ W3)
{
    const int colBase = blockIdx.x * 64;
    const int ky = blockIdx.y;
    const int kBeg = ky * 512;

    __shared__ float As[16][64];
    __shared__ float Bs[16][64];

    const int tid = threadIdx.x;
    const int tx = tid & 15;
    const int ty = tid >> 4;
    float acc[4][4] = {};

    for (int k0 = kBeg; k0 < kBeg + 512; k0 += 16) {
        #pragma unroll
        for (int i = tid; i < 64 * 16; i += 256) {
            int m = i >> 4, kk = i & 15;
            int k = k0 + kk;
            float a;
            if (k < DD) {
                int idx = m * DD + k;
                a = g_ctx_part[0][idx] + g_ctx_part[1][idx]
                  + g_ctx_part[2][idx] + g_ctx_part[3][idx];
            } else {
                a = inp[m * DD + (k - DD)];
            }
            As[kk][m] = a;
            Bs[kk][m] = W3[(size_t)(colBase + m) * (2 * DD) + k];
        }
        __syncthreads();
        #pragma unroll
        for (int kk = 0; kk < 16; kk++) {
            float a[4], w[4];
            #pragma unroll
            for (int i = 0; i < 4; i++) a[i] = As[kk][ty * 4 + i];
            #pragma unroll
            for (int j = 0; j < 4; j++) w[j] = Bs[kk][tx * 4 + j];
            #pragma unroll
            for (int i = 0; i < 4; i++)
                #pragma unroll
                for (int j = 0; j < 4; j++) acc[i][j] += a[i] * w[j];
        }
        __syncthreads();
    }
    #pragma unroll
    for (int i = 0; i < 4; i++) {
        int b = ty * 4 + i;
        #pragma unroll
        for (int j = 0; j < 4; j++) {
            int h = colBase + tx * 4 + j;
            g_fin_part[ky][b * HH + h] = acc[i][j];
        }
    }
}

// reduce partials + bias + finished mask. grid 256, block 256.
__global__ __launch_bounds__(256)
void final_reduce_kernel(const float* __restrict__ b3,
                         const unsigned char* __restrict__ fin,
                         float* __restrict__ out)
{
    int i = blockIdx.x * 256 + threadIdx.x;   // 0..65535
    int b = i >> 10;
    int h = i & 1023;
    float v = (g_fin_part[0][i] + g_fin_part[1][i])
            + (g_fin_part[2][i] + g_fin_part[3][i]) + b3[h];
    out[i] = fin[b] ? 0.0f : v;
}

// =====================================================================
// Host launcher (graph-capturable)
// =====================================================================
extern "C" void kernel_launch(void* const* d_in, const int* in_sizes, int n_in,
                              void* d_out, int out_size)
{
    const float* hidden = (const float*)d_in[0];
    const float* field  = (const float*)d_in[1];
    const float* input  = (const float*)d_in[2];
    const unsigned char* finished = (const unsigned char*)d_in[3];
    const float* W1 = (const float*)d_in[4];
    const float* b1 = (const float*)d_in[5];
    const float* W2 = (const float*)d_in[6];
    const float* b2 = (const float*)d_in[7];
    const float* W3 = (const float*)d_in[8];
    const float* b3 = (const float*)d_in[9];
    const float* W4 = (const float*)d_in[10];
    const float* b4 = (const float*)d_in[11];
    const float* W5 = (const float*)d_in[12];
    const float* b5 = (const float*)d_in[13];

    float* out = (float*)d_out;
    const int w_off = out_size - SS * BB;

    cudaFuncSetAttribute(score_mma_kernel,
                         cudaFuncAttributeMaxDynamicSharedMemorySize, SM_TOTAL);

    cvt_x_kernel<<<dim3(4096, 2), 256>>>(hidden, field);
    cvt_w_kernel<<<dim3(128, 2), 256>>>(W1, W4);
    gamma_part_kernel<<<dim3(16, 2, 4), 256>>>(input, W2, W5);
    gamma_reduce_kernel<<<dim3(128, 2), 512>>>(b2, b5);
    score_mma_kernel<<<dim3(8, RT / 128, 2), 256, SM_TOTAL>>>(b1, b4);
    softmax_kernel<<<BB, SS>>>(out, w_off);
    context_kernel<<<dim3(DD / 128, BB, 4), 128>>>(hidden);
    final_part_kernel<<<dim3(HH / 64, 4), 256>>>(input, W3);
    final_reduce_kernel<<<256, 256>>>(b3, finished, out);
}

// round 16
// speedup vs baseline: 1.1074x; 1.0209x over previous
#include <cuda_runtime.h>
#include <cuda_bf16.h>
#include <cstdint>

// Problem dims
#define BB   64
#define SS   512
#define DD   1024
#define HH   1024
#define RT   (BB*SS)
#define EPS  1e-6f

// ---------------- device scratch (static; no runtime allocs) ----------------
__device__ __align__(16) __nv_bfloat16 g_xh[2][(size_t)RT * DD];
__device__ __align__(16) __nv_bfloat16 g_xl[2][(size_t)RT * DD];
__device__ __align__(16) __nv_bfloat16 g_wh[2][(size_t)HH * DD];
__device__ __align__(16) __nv_bfloat16 g_wl[2][(size_t)HH * DD];
__device__ float g_gamma[BB * HH];
__device__ float g_alpha[BB * HH];
__device__ float g_ga_part[4][2][BB * HH];   // gamma/alpha K-split partials
__device__ float g_part[2][8][RT];
__device__ float g_wbuf[BB * SS];
__device__ float g_ctx_part[4][BB * DD];
__device__ float g_fin_part[8][BB * HH];     // final K-split partials (8-way)

// =====================================================================
// FMA-only tanh (no MUFU); abs err ~3e-7.
// =====================================================================
__device__ __forceinline__ float tanh_fma(float x) {
    float ax = fabsf(x);
    float t  = fminf(ax * 2.885390081777927f, 30.0f);
    float k  = __fadd_rn(t, 12582912.0f);
    int   n  = __float_as_int(k) - 0x4B400000;
    float fn = __fadd_rn(k, -12582912.0f);
    float f  = __fadd_rn(t, -fn);
    float p = 1.5402387e-4f;
    p = fmaf(p, f, 1.3333558e-3f);
    p = fmaf(p, f, 9.6181291e-3f);
    p = fmaf(p, f, 5.5504109e-2f);
    p = fmaf(p, f, 2.4022651e-1f);
    p = fmaf(p, f, 6.9314718e-1f);
    p = fmaf(p, f, 1.0f);
    float E = p * __int_as_float(0x3f800000 + (n << 23));
    float d = E + 1.0f;
    float y = __int_as_float(0x7EF311C3 - __float_as_int(d));
    y = y * fmaf(-d, y, 2.0f);
    y = y * fmaf(-d, y, 2.0f);
    y = y * fmaf(-d, y, 2.0f);
    float r = fmaf(-2.0f, y, 1.0f);
    return copysignf(r, x);
}

// =====================================================================
// sm_80-portable PTX helpers
// =====================================================================
__device__ __forceinline__ uint32_t smem_u32(const void* p) {
    uint32_t a;
    asm("{ .reg .u64 t; cvta.to.shared.u64 t, %1; cvt.u32.u64 %0, t; }" : "=r"(a) : "l"(p));
    return a;
}
__device__ __forceinline__ void cp_async16(uint32_t dst, const void* src) {
    asm volatile("cp.async.cg.shared.global [%0], [%1], 16;" :: "r"(dst), "l"(src));
}
__device__ __forceinline__ void cp_commit() { asm volatile("cp.async.commit_group;" ::: "memory"); }
__device__ __forceinline__ void cp_wait1()  { asm volatile("cp.async.wait_group 1;" ::: "memory"); }

__device__ __forceinline__ void ldm_x4(uint32_t a, uint32_t& r0, uint32_t& r1,
                                       uint32_t& r2, uint32_t& r3) {
    asm volatile("ldmatrix.sync.aligned.m8n8.x4.shared.b16 {%0,%1,%2,%3}, [%4];"
                 : "=r"(r0), "=r"(r1), "=r"(r2), "=r"(r3) : "r"(a));
}
__device__ __forceinline__ void mma16816(float& c0, float& c1, float& c2, float& c3,
                                         uint32_t a0, uint32_t a1, uint32_t a2, uint32_t a3,
                                         uint32_t b0, uint32_t b1) {
    asm volatile("mma.sync.aligned.m16n8k16.row.col.f32.bf16.bf16.f32 "
                 "{%0,%1,%2,%3}, {%4,%5,%6,%7}, {%8,%9}, {%0,%1,%2,%3};"
                 : "+f"(c0), "+f"(c1), "+f"(c2), "+f"(c3)
                 : "r"(a0), "r"(a1), "r"(a2), "r"(a3), "r"(b0), "r"(b1));
}

// =====================================================================
// hi/lo split packer
// =====================================================================
__device__ __forceinline__ void split_pack(float4 v0, float4 v1, uint4& hp, uint4& lp) {
    __nv_bfloat16 h0 = __float2bfloat16(v0.x), h1 = __float2bfloat16(v0.y);
    __nv_bfloat16 h2 = __float2bfloat16(v0.z), h3 = __float2bfloat16(v0.w);
    __nv_bfloat16 h4 = __float2bfloat16(v1.x), h5 = __float2bfloat16(v1.y);
    __nv_bfloat16 h6 = __float2bfloat16(v1.z), h7 = __float2bfloat16(v1.w);
    __nv_bfloat16 l0 = __float2bfloat16(v0.x - __bfloat162float(h0));
    __nv_bfloat16 l1 = __float2bfloat16(v0.y - __bfloat162float(h1));
    __nv_bfloat16 l2 = __float2bfloat16(v0.z - __bfloat162float(h2));
    __nv_bfloat16 l3 = __float2bfloat16(v0.w - __bfloat162float(h3));
    __nv_bfloat16 l4 = __float2bfloat16(v1.x - __bfloat162float(h4));
    __nv_bfloat16 l5 = __float2bfloat16(v1.y - __bfloat162float(h5));
    __nv_bfloat16 l6 = __float2bfloat16(v1.z - __bfloat162float(h6));
    __nv_bfloat16 l7 = __float2bfloat16(v1.w - __bfloat162float(h7));
    hp.x = ((uint32_t)__bfloat16_as_ushort(h1) << 16) | __bfloat16_as_ushort(h0);
    hp.y = ((uint32_t)__bfloat16_as_ushort(h3) << 16) | __bfloat16_as_ushort(h2);
    hp.z = ((uint32_t)__bfloat16_as_ushort(h5) << 16) | __bfloat16_as_ushort(h4);
    hp.w = ((uint32_t)__bfloat16_as_ushort(h7) << 16) | __bfloat16_as_ushort(h6);
    lp.x = ((uint32_t)__bfloat16_as_ushort(l1) << 16) | __bfloat16_as_ushort(l0);
    lp.y = ((uint32_t)__bfloat16_as_ushort(l3) << 16) | __bfloat16_as_ushort(l2);
    lp.z = ((uint32_t)__bfloat16_as_ushort(l5) << 16) | __bfloat16_as_ushort(l4);
    lp.w = ((uint32_t)__bfloat16_as_ushort(l7) << 16) | __bfloat16_as_ushort(l6);
}

// X convert, both z fused: grid (4096, 2), block 256.
__global__ __launch_bounds__(256)
void cvt_x_kernel(const float* __restrict__ hidden, const float* __restrict__ field) {
    const int z = blockIdx.y;
    const float* src = z ? field : hidden;
    uint4* dh = reinterpret_cast<uint4*>(g_xh[z]);
    uint4* dl = reinterpret_cast<uint4*>(g_xl[z]);
    const float4* s4 = reinterpret_cast<const float4*>(src);
    float4 v[8];
    size_t base[4];
    #pragma unroll
    for (int it = 0; it < 4; ++it) {
        size_t g8 = (size_t)blockIdx.x * 1024 + it * 256 + threadIdx.x;
        base[it] = g8;
        v[it * 2]     = s4[g8 * 2];
        v[it * 2 + 1] = s4[g8 * 2 + 1];
    }
    #pragma unroll
    for (int it = 0; it < 4; ++it) {
        uint4 hp, lp;
        split_pack(v[it * 2], v[it * 2 + 1], hp, lp);
        dh[base[it]] = hp;
        dl[base[it]] = lp;
    }
}
// W convert, both z fused: grid (128, 2), block 256.
__global__ __launch_bounds__(256)
void cvt_w_kernel(const float* __restrict__ W1g, const float* __restrict__ W4g) {
    const int z = blockIdx.y;
    const float* src = z ? W4g : W1g;
    uint4* dh = reinterpret_cast<uint4*>(g_wh[z]);
    uint4* dl = reinterpret_cast<uint4*>(g_wl[z]);
    const float4* s4 = reinterpret_cast<const float4*>(src);
    #pragma unroll
    for (int it = 0; it < 4; ++it) {
        size_t g8 = (size_t)blockIdx.x * 1024 + it * 256 + threadIdx.x;
        float4 v0 = s4[g8 * 2];
        float4 v1 = s4[g8 * 2 + 1];
        uint4 hp, lp;
        split_pack(v0, v1, hp, lp);
        dh[g8] = hp;
        dl[g8] = lp;
    }
}

// =====================================================================
// gamma/alpha GEMM, K-split 4-way: grid (16, 2, 4), block 256.
// =====================================================================
__global__ __launch_bounds__(256)
void gamma_part_kernel(const float* __restrict__ inp,
                       const float* __restrict__ W2, const float* __restrict__ W5)
{
    const int z  = blockIdx.y;
    const int ky = blockIdx.z;
    const float* W = z ? W5 : W2;
    float* out = g_ga_part[ky][z];

    const int colBase = blockIdx.x * 64;
    const int kBeg = ky * 256;
    __shared__ float As[16][64];
    __shared__ float Bs[16][64];

    const int tid = threadIdx.x;
    const int tx = tid & 15;
    const int ty = tid >> 4;
    float acc[4][4] = {};

    for (int k0 = kBeg; k0 < kBeg + 256; k0 += 16) {
        #pragma unroll
        for (int i = tid; i < 64 * 16; i += 256) {
            int m = i >> 4, kk = i & 15;
            As[kk][m] = inp[m * DD + k0 + kk];
            Bs[kk][m] = W[(colBase + m) * DD + k0 + kk];
        }
        __syncthreads();
        #pragma unroll
        for (int kk = 0; kk < 16; kk++) {
            float a[4], w[4];
            #pragma unroll
            for (int i = 0; i < 4; i++) a[i] = As[kk][ty * 4 + i];
            #pragma unroll
            for (int j = 0; j < 4; j++) w[j] = Bs[kk][tx * 4 + j];
            #pragma unroll
            for (int i = 0; i < 4; i++)
                #pragma unroll
                for (int j = 0; j < 4; j++) acc[i][j] += a[i] * w[j];
        }
        __syncthreads();
    }
    #pragma unroll
    for (int i = 0; i < 4; i++) {
        int b = ty * 4 + i;
        #pragma unroll
        for (int j = 0; j < 4; j++) {
            int h = colBase + tx * 4 + j;
            out[b * HH + h] = acc[i][j];
        }
    }
}

// reduce gamma/alpha partials + bias + tanh. grid (128, 2), block 512.
__global__ __launch_bounds__(512)
void gamma_reduce_kernel(const float* __restrict__ b2, const float* __restrict__ b5)
{
    const int z = blockIdx.y;
    const float* bias = z ? b5 : b2;
    float* out = z ? g_alpha : g_gamma;
    int i = blockIdx.x * 512 + threadIdx.x;
    int h = i & 1023;
    float v = (g_ga_part[0][z][i] + g_ga_part[1][z][i])
            + (g_ga_part[2][z][i] + g_ga_part[3][z][i]) + bias[h];
    out[i] = tanh_fma(v);
}

// =====================================================================
// Score GEMM — EXACT R11/R14/R15 structure (measured best).
// grid (8, 256, 2), block 256.
// =====================================================================
#define KCH        32
#define NCHUNK     (DD / KCH)             // 32
#define ROWB       80
#define TILEB      (128 * ROWB)            // 10240
#define STAGEB     (4 * TILEB)             // 40960
#define SM_BIAS    (2 * STAGEB)            // 81920
#define SM_GAM     (SM_BIAS + 512)
#define SM_SPART   (SM_GAM + 512)
#define SM_TOTAL   (SM_SPART + 1024)       // 83968

__global__ __launch_bounds__(256)
void score_mma_kernel(const float* __restrict__ b1g, const float* __restrict__ b4g)
{
    extern __shared__ char sm[];
    const uint32_t sb = smem_u32(sm);

    const int z       = blockIdx.z;
    const int colBase = blockIdx.x * 128;
    const int rowBase = blockIdx.y * 128;
    const int tid     = threadIdx.x;
    const int lane    = tid & 31;
    const int wid     = tid >> 5;
    const int wm      = wid >> 1;
    const int wn      = wid & 1;

    const __nv_bfloat16* Ah = g_xh[z] + (size_t)rowBase * DD;
    const __nv_bfloat16* Al = g_xl[z] + (size_t)rowBase * DD;
    const __nv_bfloat16* Bh = g_wh[z] + (size_t)colBase * DD;
    const __nv_bfloat16* Bl = g_wl[z] + (size_t)colBase * DD;
    const float* bias = z ? b4g : b1g;
    const float* gm   = z ? g_alpha : g_gamma;
    const int b_idx   = rowBase / SS;

    float* sbias = reinterpret_cast<float*>(sm + SM_BIAS);
    float* sgam  = reinterpret_cast<float*>(sm + SM_GAM);
    float* spart = reinterpret_cast<float*>(sm + SM_SPART);

    if (tid < 128) {
        sbias[tid] = bias[colBase + tid];
        sgam[tid]  = gm[b_idx * HH + colBase + tid];
    }

    auto load_stage = [&](int ch, int buf) {
        const uint32_t sbase = sb + buf * STAGEB;
        const int kb = ch * KCH * 2;
        #pragma unroll
        for (int q = 0; q < 8; ++q) {
            int idx  = q * 256 + tid;
            int tile = idx >> 9;
            int rem  = idx & 511;
            int row  = rem >> 2;
            int seg  = (rem & 3) << 4;
            const char* src;
            switch (tile) {
                case 0:  src = (const char*)(Ah + (size_t)row * DD) + kb + seg; break;
                case 1:  src = (const char*)(Al + (size_t)row * DD) + kb + seg; break;
                case 2:  src = (const char*)(Bh + (size_t)row * DD) + kb + seg; break;
                default: src = (const char*)(Bl + (size_t)row * DD) + kb + seg; break;
            }
            cp_async16(sbase + tile * TILEB + row * ROWB + seg, src);
        }
    };

    float c[2][8][4];
    #pragma unroll
    for (int mt = 0; mt < 2; ++mt)
        #pragma unroll
        for (int j = 0; j < 8; ++j)
            #pragma unroll
            for (int e = 0; e < 4; ++e) c[mt][j][e] = 0.0f;

    load_stage(0, 0); cp_commit();
    load_stage(1, 1); cp_commit();

    const int t4  = lane >> 3;
    const int r8  = lane & 7;

    for (int ch = 0; ch < NCHUNK; ++ch) {
        cp_wait1();
        __syncthreads();
        const uint32_t sbase = sb + (ch & 1) * STAGEB;
        const uint32_t aHi = sbase;
        const uint32_t aLo = sbase + TILEB;
        const uint32_t bHi = sbase + 2 * TILEB;
        const uint32_t bLo = sbase + 3 * TILEB;

        #pragma unroll
        for (int ks = 0; ks < 2; ++ks) {
            const int koff = ks * 32 + ((t4 >> 1) << 4);
            const int koffB = ks * 32 + ((t4 & 1) << 4);
            uint32_t ah[2][4], al[2][4];
            #pragma unroll
            for (int mt = 0; mt < 2; ++mt) {
                const int row = wm * 32 + mt * 16 + r8 + ((t4 & 1) << 3);
                ldm_x4(aHi + row * ROWB + koff, ah[mt][0], ah[mt][1], ah[mt][2], ah[mt][3]);
                ldm_x4(aLo + row * ROWB + koff, al[mt][0], al[mt][1], al[mt][2], al[mt][3]);
            }
            uint32_t bh[8][2], bl[8][2];
            #pragma unroll
            for (int nt = 0; nt < 4; ++nt) {
                const int row = wn * 64 + nt * 16 + r8 + ((t4 >> 1) << 3);
                uint32_t r0, r1, r2, r3;
                ldm_x4(bHi + row * ROWB + koffB, r0, r1, r2, r3);
                bh[nt * 2][0] = r0; bh[nt * 2][1] = r1;
                bh[nt * 2 + 1][0] = r2; bh[nt * 2 + 1][1] = r3;
                ldm_x4(bLo + row * ROWB + koffB, r0, r1, r2, r3);
                bl[nt * 2][0] = r0; bl[nt * 2][1] = r1;
                bl[nt * 2 + 1][0] = r2; bl[nt * 2 + 1][1] = r3;
            }
            #pragma unroll
            for (int mt = 0; mt < 2; ++mt)
                #pragma unroll
                for (int j = 0; j < 8; ++j)
                    mma16816(c[mt][j][0], c[mt][j][1], c[mt][j][2], c[mt][j][3],
                             ah[mt][0], ah[mt][1], ah[mt][2], ah[mt][3],
                             bh[j][0], bh[j][1]);
            #pragma unroll
            for (int mt = 0; mt < 2; ++mt)
                #pragma unroll
                for (int j = 0; j < 8; ++j)
                    mma16816(c[mt][j][0], c[mt][j][1], c[mt][j][2], c[mt][j][3],
                             ah[mt][0], ah[mt][1], ah[mt][2], ah[mt][3],
                             bl[j][0], bl[j][1]);
            #pragma unroll
            for (int mt = 0; mt < 2; ++mt)
                #pragma unroll
                for (int j = 0; j < 8; ++j)
                    mma16816(c[mt][j][0], c[mt][j][1], c[mt][j][2], c[mt][j][3],
                             al[mt][0], al[mt][1], al[mt][2], al[mt][3],
                             bh[j][0], bh[j][1]);
        }
        __syncthreads();
        if (ch + 2 < NCHUNK) load_stage(ch + 2, ch & 1);
        cp_commit();
    }

    float rsum[2][2] = {};
    #pragma unroll
    for (int mt = 0; mt < 2; ++mt) {
        #pragma unroll
        for (int j = 0; j < 8; ++j) {
            const int col0 = wn * 64 + j * 8 + (lane & 3) * 2;
            float b0 = sbias[col0], b1v = sbias[col0 + 1];
            float g0 = sgam[col0],  g1v = sgam[col0 + 1];
            rsum[mt][0] = fmaf(tanh_fma(c[mt][j][0] + b0), g0, rsum[mt][0]);
            rsum[mt][0] = fmaf(tanh_fma(c[mt][j][1] + b1v), g1v, rsum[mt][0]);
            rsum[mt][1] = fmaf(tanh_fma(c[mt][j][2] + b0), g0, rsum[mt][1]);
            rsum[mt][1] = fmaf(tanh_fma(c[mt][j][3] + b1v), g1v, rsum[mt][1]);
        }
    }
    #pragma unroll
    for (int mt = 0; mt < 2; ++mt)
        #pragma unroll
        for (int h = 0; h < 2; ++h) {
            float v = rsum[mt][h];
            v += __shfl_xor_sync(0xffffffffu, v, 1);
            v += __shfl_xor_sync(0xffffffffu, v, 2);
            rsum[mt][h] = v;
        }
    if ((lane & 3) == 0) {
        #pragma unroll
        for (int mt = 0; mt < 2; ++mt)
            #pragma unroll
            for (int h = 0; h < 2; ++h) {
                int r = wm * 32 + mt * 16 + (lane >> 2) + h * 8;
                spart[r * 2 + wn] = rsum[mt][h];
            }
    }
    __syncthreads();
    if (tid < 128)
        g_part[z][blockIdx.x][rowBase + tid] = spart[tid * 2] + spart[tid * 2 + 1];
}

// =====================================================================
// softmax combine — warp-shuffle reductions (2 barriers per reduce).
// grid 64, block 512. Exact reference semantics (reassociation only).
// =====================================================================
__device__ __forceinline__ float blk_reduce(float v, float* red, int tid, bool is_max) {
    #pragma unroll
    for (int o = 16; o > 0; o >>= 1) {
        float t = __shfl_xor_sync(0xffffffffu, v, o);
        v = is_max ? fmaxf(v, t) : (v + t);
    }
    if ((tid & 31) == 0) red[tid >> 5] = v;
    __syncthreads();
    if (tid < 32) {
        float x = (tid < 16) ? red[tid] : (is_max ? -3.4e38f : 0.0f);
        #pragma unroll
        for (int o = 8; o > 0; o >>= 1) {
            float t = __shfl_xor_sync(0xffffffffu, x, o);
            x = is_max ? fmaxf(x, t) : (x + t);
        }
        if (tid == 0) red[0] = x;
    }
    __syncthreads();
    float r = red[0];
    __syncthreads();
    return r;
}

__global__ __launch_bounds__(512)
void softmax_kernel(float* __restrict__ out, int w_off)
{
    const int b = blockIdx.x;
    const int s = threadIdx.x;
    const int r = b * SS + s;

    float sh = 0.0f, sf = 0.0f;
    #pragma unroll
    for (int nb = 0; nb < 8; nb++) {
        sh += g_part[0][nb][r];
        sf += g_part[1][nb][r];
    }

    __shared__ float red[16];

    float mh = blk_reduce(sh, red, s, true);
    float wh = expf(sh - mh);
    float sumh = blk_reduce(wh, red, s, false);
    wh = wh / (EPS + sumh);

    float mf = blk_reduce(sf, red, s, true);
    float wf = expf(sf - mf);
    float sumf = blk_reduce(wf, red, s, false);
    wf = wf / (EPS + sumf);

    float p = wh * wf;
    float sump = blk_reduce(p, red, s, false);
    float w = p / (EPS + sump);

    g_wbuf[r] = w;
    out[w_off + s * BB + b] = w;
}

// =====================================================================
// context partials: split s 4 ways
// =====================================================================
__global__ __launch_bounds__(128)
void context_kernel(const float* __restrict__ hid)
{
    const int b = blockIdx.y;
    const int d = blockIdx.x * 128 + threadIdx.x;
    const int s0 = blockIdx.z * 128;

    __shared__ float ws[128];
    ws[threadIdx.x] = g_wbuf[b * SS + s0 + threadIdx.x];
    __syncthreads();

    const float* base = hid + (size_t)b * SS * DD + (size_t)s0 * DD + d;
    float acc = 0.0f;
    #pragma unroll 8
    for (int s = 0; s < 128; s++)
        acc = fmaf(base[(size_t)s * DD], ws[s], acc);
    g_ctx_part[blockIdx.z][b * DD + d] = acc;
}

// =====================================================================
// final GEMM, K-split 8-way: grid (16, 8). K range ky*256..+256.
// =====================================================================
__global__ __launch_bounds__(256)
void final_part_kernel(const float* __restrict__ inp, const float* __restrict__ W3)
{
    const int colBase = blockIdx.x * 64;
    const int ky = blockIdx.y;
    const int kBeg = ky * 256;

    __shared__ float As[16][64];
    __shared__ float Bs[16][64];

    const int tid = threadIdx.x;
    const int tx = tid & 15;
    const int ty = tid >> 4;
    float acc[4][4] = {};

    for (int k0 = kBeg; k0 < kBeg + 256; k0 += 16) {
        #pragma unroll
        for (int i = tid; i < 64 * 16; i += 256) {
            int m = i >> 4, kk = i & 15;
            int k = k0 + kk;
            float a;
            if (k < DD) {
                int idx = m * DD + k;
                a = g_ctx_part[0][idx] + g_ctx_part[1][idx]
                  + g_ctx_part[2][idx] + g_ctx_part[3][idx];
            } else {
                a = inp[m * DD + (k - DD)];
            }
            As[kk][m] = a;
            Bs[kk][m] = W3[(size_t)(colBase + m) * (2 * DD) + k];
        }
        __syncthreads();
        #pragma unroll
        for (int kk = 0; kk < 16; kk++) {
            float a[4], w[4];
            #pragma unroll
            for (int i = 0; i < 4; i++) a[i] = As[kk][ty * 4 + i];
            #pragma unroll
            for (int j = 0; j < 4; j++) w[j] = Bs[kk][tx * 4 + j];
            #pragma unroll
            for (int i = 0; i < 4; i++)
                #pragma unroll
                for (int j = 0; j < 4; j++) acc[i][j] += a[i] * w[j];
        }
        __syncthreads();
    }
    #pragma unroll
    for (int i = 0; i < 4; i++) {
        int b = ty * 4 + i;
        #pragma unroll
        for (int j = 0; j < 4; j++) {
            int h = colBase + tx * 4 + j;
            g_fin_part[ky][b * HH + h] = acc[i][j];
        }
    }
}

// reduce 8 partials + bias + finished mask. grid 256, block 256.
__global__ __launch_bounds__(256)
void final_reduce_kernel(const float* __restrict__ b3,
                         const unsigned char* __restrict__ fin,
                         float* __restrict__ out)
{
    int i = blockIdx.x * 256 + threadIdx.x;
    int b = i >> 10;
    int h = i & 1023;
    float v = ((g_fin_part[0][i] + g_fin_part[1][i]) + (g_fin_part[2][i] + g_fin_part[3][i]))
            + ((g_fin_part[4][i] + g_fin_part[5][i]) + (g_fin_part[6][i] + g_fin_part[7][i]))
            + b3[h];
    out[i] = fin[b] ? 0.0f : v;
}

// =====================================================================
// Host launcher (graph-capturable)
// =====================================================================
extern "C" void kernel_launch(void* const* d_in, const int* in_sizes, int n_in,
                              void* d_out, int out_size)
{
    const float* hidden = (const float*)d_in[0];
    const float* field  = (const float*)d_in[1];
    const float* input  = (const float*)d_in[2];
    const unsigned char* finished = (const unsigned char*)d_in[3];
    const float* W1 = (const float*)d_in[4];
    const float* b1 = (const float*)d_in[5];
    const float* W2 = (const float*)d_in[6];
    const float* b2 = (const float*)d_in[7];
    const float* W3 = (const float*)d_in[8];
    const float* b3 = (const float*)d_in[9];
    const float* W4 = (const float*)d_in[10];
    const float* b4 = (const float*)d_in[11];
    const float* W5 = (const float*)d_in[12];
    const float* b5 = (const float*)d_in[13];

    float* out = (float*)d_out;
    const int w_off = out_size - SS * BB;

    cudaFuncSetAttribute(score_mma_kernel,
                         cudaFuncAttributeMaxDynamicSharedMemorySize, SM_TOTAL);

    cvt_x_kernel<<<dim3(4096, 2), 256>>>(hidden, field);
    cvt_w_kernel<<<dim3(128, 2), 256>>>(W1, W4);
    gamma_part_kernel<<<dim3(16, 2, 4), 256>>>(input, W2, W5);
    gamma_reduce_kernel<<<dim3(128, 2), 512>>>(b2, b5);
    score_mma_kernel<<<dim3(8, RT / 128, 2), 256, SM_TOTAL>>>(b1, b4);
    softmax_kernel<<<BB, SS>>>(out, w_off);
    context_kernel<<<dim3(DD / 128, BB, 4), 128>>>(hidden);
    final_part_kernel<<<dim3(HH / 64, 8), 256>>>(input, W3);
    final_reduce_kernel<<<256, 256>>>(b3, finished, out);
}